// round 8
// baseline (speedup 1.0000x reference)
#include <cuda_runtime.h>
#include <math.h>
#include <stdint.h>

typedef unsigned long long ull;

// ---------------- problem constants ----------------
#define B 2
#define C 192
#define HEADS 6
#define ZP 32
#define NPOS (B*ZP*ZP*ZP)          // 65536
#define NW 256
#define DEPTH 4
#define TBL 675

// weight-transpose scratch offsets (floats)
#define QO 0
#define PO 442368
#define F1O 589824
#define F2O 1179648
#define RO 1769472
#define WT_TOTAL 1794048

// ---------------- scratch ----------------
__device__ float g_e  [(size_t)NPOS * C];
__device__ float g_w  [(size_t)NPOS * C];
__device__ float g_qkv[(size_t)NPOS * 3 * C];
__device__ float g_o  [(size_t)NPOS * C];
__device__ float g_h  [(size_t)NPOS * 4 * C];
__device__ float g_wt [WT_TOTAL];
__device__ float g_zeros[192];

// ---------------- helpers ----------------
__device__ __forceinline__ float gelu_f(float v){
    return 0.5f * v * (1.0f + erff(v * 0.70710678118654752f));
}
// f32x2 (attention)
__device__ __forceinline__ void fma2(ull &d, ull a, ull b){
    asm("fma.rn.f32x2 %0, %1, %2, %0;" : "+l"(d) : "l"(a), "l"(b));
}
__device__ __forceinline__ ull dup2(float x){
    ull r; asm("mov.b64 %0, {%1, %1};" : "=l"(r) : "f"(x)); return r;
}
__device__ __forceinline__ float2 unpack2(ull v){
    float2 f; asm("mov.b64 {%0, %1}, %2;" : "=f"(f.x), "=f"(f.y) : "l"(v)); return f;
}
// tf32 mma.sync (sm_80+ baseline — compiles at compute_103)
__device__ __forceinline__ void mma_tf32(float* d, const uint32_t* a, const uint32_t* b){
    asm volatile(
        "mma.sync.aligned.m16n8k8.row.col.f32.tf32.tf32.f32 "
        "{%0,%1,%2,%3}, {%4,%5,%6,%7}, {%8,%9}, {%0,%1,%2,%3};"
        : "+f"(d[0]), "+f"(d[1]), "+f"(d[2]), "+f"(d[3])
        : "r"(a[0]), "r"(a[1]), "r"(a[2]), "r"(a[3]), "r"(b[0]), "r"(b[1]));
}
// round-to-nearest tf32 (debiases the HW RZ truncation)
__device__ __forceinline__ float tf32_rna(float x){
    uint32_t r; asm("cvt.rna.tf32.f32 %0, %1;" : "=r"(r) : "f"(x));
    return __uint_as_float(r);
}
__device__ __forceinline__ float4 rna4(float4 v){
    v.x = tf32_rna(v.x); v.y = tf32_rna(v.y);
    v.z = tf32_rna(v.z); v.w = tf32_rna(v.w);
    return v;
}

// ================= tf32 mma.sync GEMM =================
// D[M,N] = act(A[M,K] @ Wt[N,K]^T + bias)  (+= if BETA)
// CTA tile 128 x NT, 8 warps (4x2), warp tile 32 x NT/2, Kc=32, double-buffered.
// NT must divide N exactly (no guards).
template<int NT, int ACT, int BETA>
__global__ __launch_bounds__(256)
void gemm_mma(const float* __restrict__ A, const float* __restrict__ Bw,
              const float* __restrict__ bias, float* __restrict__ Cm,
              int N, int K)
{
    extern __shared__ float smem[];
    constexpr int ASZ = 128 * 36;
    constexpr int BSZ = NT * 36;
    constexpr int NBP = NT / 32;     // B float4 loads per thread per k-tile
    constexpr int NIW = NT / 16;     // n8-tiles per warp (= NT/2/8)
    float* Asm[2] = { smem, smem + ASZ };
    float* Bsm[2] = { smem + 2 * ASZ, smem + 2 * ASZ + BSZ };

    const int t = threadIdx.x;
    const int lane = t & 31, wid = t >> 5;
    const int warpM = (wid >> 1) * 32;
    const int warpN = (wid & 1) * (NT / 2);
    const int g = lane >> 2, tg = lane & 3;
    const int bm = blockIdx.y << 7;
    const int bn = blockIdx.x * NT;
    const int K4 = K >> 2;
    const int nk = K >> 5;

    const float4* A4 = (const float4*)A;
    const float4* B4 = (const float4*)Bw;
    const int lrow = t >> 3;        // 0..31
    const int lk4  = t & 7;
    int aBase[4]; int aSm[4];
#pragma unroll
    for (int i = 0; i < 4; i++) {
        int row = lrow + i * 32;
        aBase[i] = (bm + row) * K4 + lk4;
        aSm[i] = row * 36 + lk4 * 4;
    }
    int bBase[NBP]; int bSm[NBP];
#pragma unroll
    for (int i = 0; i < NBP; i++) {
        int row = lrow + i * 32;
        bBase[i] = (bn + row) * K4 + lk4;
        bSm[i] = row * 36 + lk4 * 4;
    }

    float4 pa[4], pb[NBP];
#pragma unroll
    for (int i = 0; i < 4; i++)   pa[i] = A4[aBase[i]];
#pragma unroll
    for (int i = 0; i < NBP; i++) pb[i] = B4[bBase[i]];
#pragma unroll
    for (int i = 0; i < 4; i++)   *(float4*)&Asm[0][aSm[i]] = rna4(pa[i]);
#pragma unroll
    for (int i = 0; i < NBP; i++) *(float4*)&Bsm[0][bSm[i]] = rna4(pb[i]);

    float acc[2][NIW][4];
#pragma unroll
    for (int mi = 0; mi < 2; mi++)
#pragma unroll
        for (int ni = 0; ni < NIW; ni++)
#pragma unroll
            for (int j = 0; j < 4; j++) acc[mi][ni][j] = 0.f;

    for (int kt = 0; kt < nk; kt++) {
        __syncthreads();
        const int buf = kt & 1;
        const bool more = (kt + 1 < nk);
        if (more) {
            int ko = (kt + 1) * 8;
#pragma unroll
            for (int i = 0; i < 4; i++)   pa[i] = A4[aBase[i] + ko];
#pragma unroll
            for (int i = 0; i < NBP; i++) pb[i] = B4[bBase[i] + ko];
        }
        const uint32_t* Asu = (const uint32_t*)Asm[buf];
        const uint32_t* Bsu = (const uint32_t*)Bsm[buf];
#pragma unroll
        for (int ks = 0; ks < 4; ks++) {
            const int k0 = ks * 8;
            uint32_t af[2][4];
#pragma unroll
            for (int mi = 0; mi < 2; mi++) {
                int r = (warpM + mi * 16 + g) * 36 + k0 + tg;
                af[mi][0] = Asu[r];
                af[mi][1] = Asu[r + 8 * 36];
                af[mi][2] = Asu[r + 4];
                af[mi][3] = Asu[r + 8 * 36 + 4];
            }
#pragma unroll
            for (int ni = 0; ni < NIW; ni++) {
                uint32_t bf[2];
                int r = (warpN + ni * 8 + g) * 36 + k0 + tg;
                bf[0] = Bsu[r];
                bf[1] = Bsu[r + 4];
                mma_tf32(acc[0][ni], af[0], bf);
                mma_tf32(acc[1][ni], af[1], bf);
            }
        }
        if (more) {
            const int nb = buf ^ 1;
#pragma unroll
            for (int i = 0; i < 4; i++)   *(float4*)&Asm[nb][aSm[i]] = rna4(pa[i]);
#pragma unroll
            for (int i = 0; i < NBP; i++) *(float4*)&Bsm[nb][bSm[i]] = rna4(pb[i]);
        }
    }

    // epilogue: direct float2 stores
#pragma unroll
    for (int mi = 0; mi < 2; mi++) {
        int r0 = bm + warpM + mi * 16 + g;
#pragma unroll
        for (int ni = 0; ni < NIW; ni++) {
            int cb = bn + warpN + ni * 8 + 2 * tg;
            float b0 = bias[cb], b1 = bias[cb + 1];
            float v0 = acc[mi][ni][0] + b0, v1 = acc[mi][ni][1] + b1;
            float v2 = acc[mi][ni][2] + b0, v3 = acc[mi][ni][3] + b1;
            if (ACT) { v0 = gelu_f(v0); v1 = gelu_f(v1); v2 = gelu_f(v2); v3 = gelu_f(v3); }
            size_t o0 = (size_t)r0 * N + cb;
            size_t o1 = (size_t)(r0 + 8) * N + cb;
            if (BETA) {
                float2 x0 = *(const float2*)&Cm[o0];
                float2 x1 = *(const float2*)&Cm[o1];
                v0 += x0.x; v1 += x0.y; v2 += x1.x; v3 += x1.y;
            }
            *(float2*)&Cm[o0] = make_float2(v0, v1);
            *(float2*)&Cm[o1] = make_float2(v2, v3);
        }
    }
}

// ---------------- weight transpose: [K,N] -> [N,K] ----------------
__global__ void transpose_w(const float* __restrict__ src, float* __restrict__ dst,
                            int K, int N)
{
    int idx = blockIdx.x * blockDim.x + threadIdx.x;
    if (idx >= K * N) return;
    int k = idx / N, n = idx % N;
    dst[(size_t)n * K + k] = src[idx];
}

// ---------------- warp-per-token LayerNorm ----------------
// mode: 0 flat, 1 window partition, 2 window partition + roll
__global__ __launch_bounds__(256)
void ln2_kernel(const float* __restrict__ src, float* __restrict__ dst,
                const float* __restrict__ g, const float* __restrict__ b, int mode)
{
    const int lane = threadIdx.x & 31;
    const int tok = blockIdx.x * 8 + (threadIdx.x >> 5);
    int spos;
    if (mode == 0) {
        spos = tok;
    } else {
        int n = tok & 127, wi = (tok >> 7) & 255, bb = tok >> 15;
        int zw = wi >> 4, hw = (wi >> 2) & 3, ww = wi & 3;
        int z = zw * 2 + (n >> 6), h = hw * 8 + ((n >> 3) & 7), w = ww * 8 + (n & 7);
        if (mode == 2) { z = (z + 1) & 31; h = (h + 4) & 31; w = (w + 4) & 31; }
        spos = ((bb * 32 + z) * 32 + h) * 32 + w;
    }
    const float* sp = src + (size_t)spos * C;
    float v[6]; float s = 0.f, s2 = 0.f;
#pragma unroll
    for (int j = 0; j < 6; j++) { v[j] = sp[lane + 32*j]; s += v[j]; s2 += v[j]*v[j]; }
#pragma unroll
    for (int o = 16; o > 0; o >>= 1) {
        s  += __shfl_xor_sync(0xffffffffu, s,  o);
        s2 += __shfl_xor_sync(0xffffffffu, s2, o);
    }
    float m = s * (1.0f/192.0f);
    float rstd = rsqrtf(s2 * (1.0f/192.0f) - m*m + 1e-5f);
    float* dp = dst + (size_t)tok * C;
#pragma unroll
    for (int j = 0; j < 6; j++) {
        int c = lane + 32*j;
        dp[c] = (v[j] - m) * rstd * g[c] + b[c];
    }
}

// ---------------- fused window-merge + residual add + LayerNorm ----------------
__global__ __launch_bounds__(256)
void lnfuse_kernel(float* __restrict__ e, const float* __restrict__ wwin,
                   float* __restrict__ dst,
                   const float* __restrict__ g, const float* __restrict__ b, int shifted)
{
    const int lane = threadIdx.x & 31;
    const int pos = blockIdx.x * 8 + (threadIdx.x >> 5);
    int ww2 = pos & 31, hh = (pos >> 5) & 31, z = (pos >> 10) & 31, bb = pos >> 15;
    int sz = shifted ? 1 : 0, s4 = shifted ? 4 : 0;
    int z2 = (z - sz) & 31, h2 = (hh - s4) & 31, w2 = (ww2 - s4) & 31;
    int wi = ((z2 >> 1) << 4) | ((h2 >> 3) << 2) | (w2 >> 3);
    int n  = ((z2 & 1) << 6) | ((h2 & 7) << 3) | (w2 & 7);
    int tok = (bb * 256 + wi) * 128 + n;

    float* ep = e + (size_t)pos * C;
    const float* wp = wwin + (size_t)tok * C;
    float v[6]; float s = 0.f, s2 = 0.f;
#pragma unroll
    for (int j = 0; j < 6; j++) {
        int c = lane + 32*j;
        float a = ep[c] + wp[c];
        ep[c] = a;
        v[j] = a; s += a; s2 += a*a;
    }
#pragma unroll
    for (int o = 16; o > 0; o >>= 1) {
        s  += __shfl_xor_sync(0xffffffffu, s,  o);
        s2 += __shfl_xor_sync(0xffffffffu, s2, o);
    }
    float m = s * (1.0f/192.0f);
    float rstd = rsqrtf(s2 * (1.0f/192.0f) - m*m + 1e-5f);
    float* dp = dst + (size_t)pos * C;
#pragma unroll
    for (int j = 0; j < 6; j++) {
        int c = lane + 32*j;
        dp[c] = (v[j] - m) * rstd * g[c] + b[c];
    }
}

// ---------------- register-tiled window attention (f32x2) ----------------
#define OQ 0
#define OK_ 4224
#define OV 8448
#define OS 13056
#define ORP 29952
#define ORID 30628
#define ATTN_SMEM_F 30756

__global__ __launch_bounds__(256)
void attn2_kernel(const float* __restrict__ rpb, int shifted)
{
    extern __shared__ float sm[];
    float* Qt = sm + OQ;
    float* Kt = sm + OK_;
    float* Vs = sm + OV;
    float* Ss = sm + OS;
    float* rpb_s = sm + ORP;
    int* rid_s = (int*)(sm + ORID);

    const int win = blockIdx.x;
    const int hh  = blockIdx.y;
    const int t = threadIdx.x;
    const int tx = t & 15, ty = t >> 4;
    const float scale = 0.1767766952966369f;

    for (int e = t; e < 4096; e += 256) {
        int n = e >> 5, d = e & 31;
        size_t base = ((size_t)(win * 128 + n)) * (3 * C) + hh * 32 + d;
        Qt[d * 132 + n] = g_qkv[base] * scale;
        Kt[d * 132 + n] = g_qkv[base + C];
        Vs[n * 36 + d]  = g_qkv[base + 2 * C];
    }
    for (int e = t; e < TBL; e += 256) rpb_s[e] = rpb[e * HEADS + hh];
    int wloc = win & 255;
    int zw = wloc >> 4, hw = (wloc >> 2) & 3, ww = wloc & 3;
    if (shifted && t < 128) {
        int z = zw * 2 + (t >> 6), h = hw * 8 + ((t >> 3) & 7), w = ww * 8 + (t & 7);
        rid_s[t] = (z < 30 ? 0 : (z < 31 ? 1 : 2)) * 9
                 + (h < 24 ? 0 : (h < 28 ? 1 : 2)) * 3
                 + (w < 24 ? 0 : (w < 28 ? 1 : 2));
    }
    __syncthreads();

    ull acc[8][4];
#pragma unroll
    for (int r = 0; r < 8; r++)
#pragma unroll
        for (int j = 0; j < 4; j++) acc[r][j] = 0ull;
#pragma unroll 4
    for (int d = 0; d < 32; d++) {
        float4 q0 = *(const float4*)&Qt[d*132 + ty*4];
        float4 q1 = *(const float4*)&Qt[d*132 + 64 + ty*4];
        ulonglong2 k01 = *(const ulonglong2*)&Kt[d*132 + tx*4];
        ulonglong2 k23 = *(const ulonglong2*)&Kt[d*132 + 64 + tx*4];
        ull kp[4] = {k01.x, k01.y, k23.x, k23.y};
        float qf[8] = {q0.x, q0.y, q0.z, q0.w, q1.x, q1.y, q1.z, q1.w};
#pragma unroll
        for (int r = 0; r < 8; r++) {
            ull qd = dup2(qf[r]);
#pragma unroll
            for (int j = 0; j < 4; j++) fma2(acc[r][j], qd, kp[j]);
        }
    }
#pragma unroll
    for (int rr = 0; rr < 8; rr++) {
        int n = (rr < 4 ? ty*4 + rr : 64 + ty*4 + rr - 4);
        int zn = n >> 6, hn = (n >> 3) & 7, wn = n & 7;
        int ridn = shifted ? rid_s[n] : 0;
#pragma unroll
        for (int j = 0; j < 4; j++) {
            float2 v = unpack2(acc[rr][j]);
            int mb = (j < 2 ? tx*4 + 2*j : 64 + tx*4 + 2*(j - 2));
            {
                int m = mb;
                int zm = m >> 6, hm = (m >> 3) & 7, wm = m & 7;
                int idx = (zn - zm + 1) * 225 + (hn - hm + 7) * 15 + (wn - wm + 7);
                v.x += rpb_s[idx];
                if (shifted && rid_s[m] != ridn) v.x -= 100.0f;
            }
            {
                int m = mb + 1;
                int zm = m >> 6, hm = (m >> 3) & 7, wm = m & 7;
                int idx = (zn - zm + 1) * 225 + (hn - hm + 7) * 15 + (wn - wm + 7);
                v.y += rpb_s[idx];
                if (shifted && rid_s[m] != ridn) v.y -= 100.0f;
            }
            *(float2*)&Ss[n * 132 + mb] = v;
        }
    }
    __syncthreads();

    {
        int n = t >> 1, half = t & 1;
        float* row = &Ss[n * 132 + half * 64];
        float mx = -1e30f;
#pragma unroll
        for (int j = 0; j < 16; j++) {
            float4 v = *(const float4*)&row[j * 4];
            mx = fmaxf(mx, fmaxf(fmaxf(v.x, v.y), fmaxf(v.z, v.w)));
        }
        mx = fmaxf(mx, __shfl_xor_sync(0xffffffffu, mx, 1));
        float sum = 0.f;
#pragma unroll
        for (int j = 0; j < 16; j++) {
            float4 v = *(float4*)&row[j * 4];
            v.x = __expf(v.x - mx); v.y = __expf(v.y - mx);
            v.z = __expf(v.z - mx); v.w = __expf(v.w - mx);
            sum += v.x + v.y + v.z + v.w;
            *(float4*)&row[j * 4] = v;
        }
        sum += __shfl_xor_sync(0xffffffffu, sum, 1);
        float inv = 1.0f / sum;
#pragma unroll
        for (int j = 0; j < 16; j++) {
            float4 v = *(float4*)&row[j * 4];
            v.x *= inv; v.y *= inv; v.z *= inv; v.w *= inv;
            *(float4*)&row[j * 4] = v;
        }
    }
    __syncthreads();

    {
        int r0 = (t >> 2) * 2;
        int d0 = (t & 3) * 8;
        ull av[2][4];
#pragma unroll
        for (int i = 0; i < 2; i++)
#pragma unroll
            for (int j = 0; j < 4; j++) av[i][j] = 0ull;
#pragma unroll 8
        for (int m = 0; m < 128; m++) {
            float s0 = Ss[r0 * 132 + m];
            float s1 = Ss[(r0 + 1) * 132 + m];
            ulonglong2 v01 = *(const ulonglong2*)&Vs[m * 36 + d0];
            ulonglong2 v23 = *(const ulonglong2*)&Vs[m * 36 + d0 + 4];
            ull sd0 = dup2(s0), sd1 = dup2(s1);
            fma2(av[0][0], sd0, v01.x); fma2(av[0][1], sd0, v01.y);
            fma2(av[0][2], sd0, v23.x); fma2(av[0][3], sd0, v23.y);
            fma2(av[1][0], sd1, v01.x); fma2(av[1][1], sd1, v01.y);
            fma2(av[1][2], sd1, v23.x); fma2(av[1][3], sd1, v23.y);
        }
#pragma unroll
        for (int i = 0; i < 2; i++) {
            float of[8];
#pragma unroll
            for (int j = 0; j < 4; j++) {
                float2 v = unpack2(av[i][j]);
                of[2*j] = v.x; of[2*j+1] = v.y;
            }
            size_t ob = ((size_t)(win * 128 + r0 + i)) * C + hh * 32 + d0;
            *(float4*)&g_o[ob]     = make_float4(of[0], of[1], of[2], of[3]);
            *(float4*)&g_o[ob + 4] = make_float4(of[4], of[5], of[6], of[7]);
        }
    }
}

// ---------------- patch-embed gather / recon scatter ----------------
__global__ void gather_kernel(const float* __restrict__ x, float* __restrict__ xg)
{
    int idx = blockIdx.x * blockDim.x + threadIdx.x;
    if (idx >= NPOS * 128) return;
    int t = idx & 127, pos = idx >> 7;
    int w = pos & 31, h = (pos >> 5) & 31, z = (pos >> 10) & 31, b = pos >> 15;
    int c4 = t >> 5, i = (t >> 4) & 1, j = (t >> 2) & 3, k = t & 3;
    xg[idx] = x[((((size_t)b * 4 + c4) * 64 + 2 * z + i) * 128 + 4 * h + j) * 128 + 4 * w + k];
}

__global__ void scatter_kernel(const float* __restrict__ rec, const float* __restrict__ rec_b,
                               float* __restrict__ out)
{
    int idx = blockIdx.x * blockDim.x + threadIdx.x;
    if (idx >= NPOS * 128) return;
    int t = idx & 127, pos = idx >> 7;
    int w = pos & 31, h = (pos >> 5) & 31, z = (pos >> 10) & 31, b = pos >> 15;
    int o = t >> 5, i = (t >> 4) & 1, j = (t >> 2) & 3, k = t & 3;
    out[((((size_t)b * 4 + o) * 64 + 2 * z + i) * 128 + 4 * h + j) * 128 + 4 * w + k]
        = rec[idx] + rec_b[o];
}

// ---------------- host launcher ----------------
extern "C" void kernel_launch(void* const* d_in, const int* in_sizes, int n_in,
                              void* d_out, int out_size)
{
    const float* x       = (const float*)d_in[0];
    const float* pe_w    = (const float*)d_in[1];
    const float* pe_b    = (const float*)d_in[2];
    const float* pe_ln_g = (const float*)d_in[3];
    const float* pe_ln_b = (const float*)d_in[4];
    const float* ln1_g   = (const float*)d_in[5];
    const float* ln1_b   = (const float*)d_in[6];
    const float* qkv_w   = (const float*)d_in[7];
    const float* qkv_b   = (const float*)d_in[8];
    const float* proj_w  = (const float*)d_in[9];
    const float* proj_b  = (const float*)d_in[10];
    const float* rpb     = (const float*)d_in[11];
    const float* ln2_g   = (const float*)d_in[12];
    const float* ln2_b   = (const float*)d_in[13];
    const float* fc1_w   = (const float*)d_in[14];
    const float* fc1_b   = (const float*)d_in[15];
    const float* fc2_w   = (const float*)d_in[16];
    const float* fc2_b   = (const float*)d_in[17];
    const float* rec_w   = (const float*)d_in[18];
    const float* rec_b   = (const float*)d_in[19];
    float* out = (float*)d_out;

    float *e, *w, *qkv, *h, *o, *wt, *zeros;
    cudaGetSymbolAddress((void**)&e,     g_e);
    cudaGetSymbolAddress((void**)&w,     g_w);
    cudaGetSymbolAddress((void**)&qkv,   g_qkv);
    cudaGetSymbolAddress((void**)&h,     g_h);
    cudaGetSymbolAddress((void**)&o,     g_o);
    cudaGetSymbolAddress((void**)&wt,    g_wt);
    cudaGetSymbolAddress((void**)&zeros, g_zeros);

    const int ATTN_SMEM = ATTN_SMEM_F * (int)sizeof(float);
    cudaFuncSetAttribute(attn2_kernel, cudaFuncAttributeMaxDynamicSharedMemorySize, ATTN_SMEM);
    const int GS192 = (2 * 128 * 36 + 2 * 192 * 36) * 4;  // 92160
    const int GS128 = (2 * 128 * 36 + 2 * 128 * 36) * 4;  // 73728
    cudaFuncSetAttribute(gemm_mma<192,0,0>, cudaFuncAttributeMaxDynamicSharedMemorySize, GS192);
    cudaFuncSetAttribute(gemm_mma<192,1,0>, cudaFuncAttributeMaxDynamicSharedMemorySize, GS192);
    cudaFuncSetAttribute(gemm_mma<192,0,1>, cudaFuncAttributeMaxDynamicSharedMemorySize, GS192);
    cudaFuncSetAttribute(gemm_mma<128,0,0>, cudaFuncAttributeMaxDynamicSharedMemorySize, GS128);

    // ---- weight transposes ([K,N] -> [N,K]) ----
    for (int d = 0; d < DEPTH; d++) {
        transpose_w<<<(192*576 + 255)/256, 256>>>(qkv_w + (size_t)d*192*576, wt + QO  + (size_t)d*110592, 192, 576);
        transpose_w<<<(192*192 + 255)/256, 256>>>(proj_w + (size_t)d*192*192, wt + PO  + (size_t)d*36864, 192, 192);
        transpose_w<<<(192*768 + 255)/256, 256>>>(fc1_w + (size_t)d*192*768, wt + F1O + (size_t)d*147456, 192, 768);
        transpose_w<<<(768*192 + 255)/256, 256>>>(fc2_w + (size_t)d*768*192, wt + F2O + (size_t)d*147456, 768, 192);
    }
    transpose_w<<<(192*128 + 255)/256, 256>>>(rec_w, wt + RO, 192, 128);

    // ---- patch embed: gather -> GEMM (pe_w already [N=192, K=128]) -> LN ----
    gather_kernel<<<(NPOS * 128) / 256, 256>>>(x, h);
    gemm_mma<192,0,0><<<dim3(1, NPOS/128), 256, GS192>>>(h, pe_w, pe_b, w, 192, 128);
    ln2_kernel<<<NPOS / 8, 256>>>(w, e, pe_ln_g, pe_ln_b, 0);

    // ---- transformer layers ----
    for (int d = 0; d < DEPTH; d++) {
        int sh = d & 1;
        ln2_kernel<<<NPOS / 8, 256>>>(e, w, ln1_g + d * C, ln1_b + d * C, sh ? 2 : 1);
        gemm_mma<192,0,0><<<dim3(3, NPOS/128), 256, GS192>>>(
            w, wt + QO + (size_t)d*110592, qkv_b + d * 3 * C, qkv, 3 * C, C);
        attn2_kernel<<<dim3(B * NW, HEADS), 256, ATTN_SMEM>>>(rpb + (size_t)d * TBL * HEADS, sh);
        gemm_mma<192,0,0><<<dim3(1, NPOS/128), 256, GS192>>>(
            o, wt + PO + (size_t)d*36864, proj_b + d * C, w, C, C);
        // fused: e += unwindow(w); qkv = LN2(e)
        lnfuse_kernel<<<NPOS / 8, 256>>>(e, w, qkv, ln2_g + d * C, ln2_b + d * C, sh);
        gemm_mma<192,1,0><<<dim3(4, NPOS/128), 256, GS192>>>(
            qkv, wt + F1O + (size_t)d*147456, fc1_b + d * 4 * C, h, 4 * C, C);
        gemm_mma<192,0,1><<<dim3(1, NPOS/128), 256, GS192>>>(
            h, wt + F2O + (size_t)d*147456, fc2_b + d * C, e, C, 4 * C);
    }

    // ---- reconstruction ----
    gemm_mma<128,0,0><<<dim3(1, NPOS/128), 256, GS128>>>(e, wt + RO, zeros, qkv, 128, C);
    scatter_kernel<<<(NPOS * 128) / 256, 256>>>(qkv, rec_b, out);
}

// round 9
// speedup vs baseline: 1.2545x; 1.2545x over previous
#include <cuda_runtime.h>
#include <math.h>
#include <stdint.h>

typedef unsigned long long ull;

// ---------------- problem constants ----------------
#define B 2
#define C 192
#define HEADS 6
#define ZP 32
#define NPOS (B*ZP*ZP*ZP)          // 65536
#define NW 256
#define DEPTH 4
#define TBL 675

// weight scratch offsets (floats)
#define QO 0
#define PO 442368
#define F1O 589824
#define F2O 1179648
#define RO 1769472
#define PEO 1794048
#define WT_TOTAL 1818624

// ---------------- scratch ----------------
__device__ float g_e  [(size_t)NPOS * C];
__device__ float g_w  [(size_t)NPOS * C];
__device__ float g_qkv[(size_t)NPOS * 3 * C];
__device__ float g_o  [(size_t)NPOS * C];
__device__ float g_h  [(size_t)NPOS * 4 * C];
__device__ float g_wt [WT_TOTAL];
__device__ float g_zeros[192];

// ---------------- helpers ----------------
__device__ __forceinline__ float gelu_f(float v){
    return 0.5f * v * (1.0f + erff(v * 0.70710678118654752f));
}
__device__ __forceinline__ void fma2(ull &d, ull a, ull b){
    asm("fma.rn.f32x2 %0, %1, %2, %0;" : "+l"(d) : "l"(a), "l"(b));
}
__device__ __forceinline__ ull dup2(float x){
    ull r; asm("mov.b64 %0, {%1, %1};" : "=l"(r) : "f"(x)); return r;
}
__device__ __forceinline__ float2 unpack2(ull v){
    float2 f; asm("mov.b64 {%0, %1}, %2;" : "=f"(f.x), "=f"(f.y) : "l"(v)); return f;
}
// tf32 mma.sync (sm_80 baseline)
__device__ __forceinline__ void mma_tf32(float* d, const uint32_t* a, const uint32_t* b){
    asm volatile(
        "mma.sync.aligned.m16n8k8.row.col.f32.tf32.tf32.f32 "
        "{%0,%1,%2,%3}, {%4,%5,%6,%7}, {%8,%9}, {%0,%1,%2,%3};"
        : "+f"(d[0]), "+f"(d[1]), "+f"(d[2]), "+f"(d[3])
        : "r"(a[0]), "r"(a[1]), "r"(a[2]), "r"(a[3]), "r"(b[0]), "r"(b[1]));
}
// round-to-nearest tf32 (applied once, at producers)
__device__ __forceinline__ float tf32_rna(float x){
    uint32_t r; asm("cvt.rna.tf32.f32 %0, %1;" : "=r"(r) : "f"(x));
    return __uint_as_float(r);
}
// cp.async (sm_80 baseline)
__device__ __forceinline__ uint32_t smem_u32(const void* p){
    uint32_t a;
    asm("{ .reg .u64 t; cvta.to.shared.u64 t, %1; cvt.u32.u64 %0, t; }" : "=r"(a) : "l"(p));
    return a;
}
__device__ __forceinline__ void cp16(uint32_t d, const void* s){
    asm volatile("cp.async.cg.shared.global [%0], [%1], 16;" :: "r"(d), "l"(s));
}
__device__ __forceinline__ void cp_commit(){
    asm volatile("cp.async.commit_group;");
}
template<int Npend>
__device__ __forceinline__ void cp_wait(){
    asm volatile("cp.async.wait_group %0;" :: "n"(Npend) : "memory");
}

// ================= tf32 mma.sync GEMM (pre-rounded operands, cp.async) =================
// D[M,N] = act(A[M,K] @ Wt[N,K]^T + bias)  (+= if BETA; round output if ROUT)
// CTA 128x64, 4 warps, warp tile 32x64, Kc=32, double-buffered cp.async.
#define ASZB (128 * 36 * 4)
#define BSZB (64 * 36 * 4)
template<int ACT, int BETA, int ROUT>
__global__ __launch_bounds__(128)
void gemm_mma(const float* __restrict__ A, const float* __restrict__ Bw,
              const float* __restrict__ bias, float* __restrict__ Cm,
              int N, int K)
{
    __shared__ float As[2][128 * 36];
    __shared__ float Bs[2][64 * 36];
    const int t = threadIdx.x;
    const int lane = t & 31, wid = t >> 5;
    const int warpM = wid * 32;
    const int g = lane >> 2, tg = lane & 3;
    const int bm = blockIdx.y << 7;
    const int bn = blockIdx.x << 6;
    const int K4 = K >> 2;
    const int nk = K >> 5;

    const float4* A4 = (const float4*)A;
    const float4* B4 = (const float4*)Bw;
    const int lrow = t >> 3;        // 0..15
    const int lk4  = t & 7;
    int aBase[8], aOff[8];
#pragma unroll
    for (int i = 0; i < 8; i++) {
        int row = lrow + i * 16;
        aBase[i] = (bm + row) * K4 + lk4;
        aOff[i] = (row * 36 + lk4 * 4) * 4;
    }
    int bBase[4], bOff[4];
#pragma unroll
    for (int i = 0; i < 4; i++) {
        int row = lrow + i * 16;
        bBase[i] = (bn + row) * K4 + lk4;
        bOff[i] = (row * 36 + lk4 * 4) * 4;
    }
    const uint32_t uA = smem_u32(&As[0][0]);
    const uint32_t uB = smem_u32(&Bs[0][0]);

    // prologue: stage k-tile 0 into buf 0
#pragma unroll
    for (int i = 0; i < 8; i++) cp16(uA + aOff[i], &A4[aBase[i]]);
#pragma unroll
    for (int i = 0; i < 4; i++) cp16(uB + bOff[i], &B4[bBase[i]]);
    cp_commit();

    float acc[2][8][4];
#pragma unroll
    for (int mi = 0; mi < 2; mi++)
#pragma unroll
        for (int ni = 0; ni < 8; ni++)
#pragma unroll
            for (int j = 0; j < 4; j++) acc[mi][ni][j] = 0.f;

    for (int kt = 0; kt < nk; kt++) {
        const int buf = kt & 1;
        const bool more = (kt + 1 < nk);
        if (more) {
            const int nb = buf ^ 1;
            const int ko = (kt + 1) * 8;
#pragma unroll
            for (int i = 0; i < 8; i++) cp16(uA + nb * ASZB + aOff[i], &A4[aBase[i] + ko]);
#pragma unroll
            for (int i = 0; i < 4; i++) cp16(uB + nb * BSZB + bOff[i], &B4[bBase[i] + ko]);
            cp_commit();
            cp_wait<1>();
        } else {
            cp_wait<0>();
        }
        __syncthreads();

        const uint32_t* Asu = (const uint32_t*)As[buf];
        const uint32_t* Bsu = (const uint32_t*)Bs[buf];
#pragma unroll
        for (int ks = 0; ks < 4; ks++) {
            const int k0 = ks * 8;
            uint32_t af[2][4];
#pragma unroll
            for (int mi = 0; mi < 2; mi++) {
                int r = (warpM + mi * 16 + g) * 36 + k0 + tg;
                af[mi][0] = Asu[r];
                af[mi][1] = Asu[r + 8 * 36];
                af[mi][2] = Asu[r + 4];
                af[mi][3] = Asu[r + 8 * 36 + 4];
            }
#pragma unroll
            for (int ni = 0; ni < 8; ni++) {
                uint32_t bf[2];
                int r = (ni * 8 + g) * 36 + k0 + tg;
                bf[0] = Bsu[r];
                bf[1] = Bsu[r + 4];
                mma_tf32(acc[0][ni], af[0], bf);
                mma_tf32(acc[1][ni], af[1], bf);
            }
        }
        __syncthreads();
    }

    // epilogue
#pragma unroll
    for (int mi = 0; mi < 2; mi++) {
        int r0 = bm + warpM + mi * 16 + g;
#pragma unroll
        for (int ni = 0; ni < 8; ni++) {
            int cb = bn + ni * 8 + 2 * tg;
            float b0 = bias[cb], b1 = bias[cb + 1];
            float v0 = acc[mi][ni][0] + b0, v1 = acc[mi][ni][1] + b1;
            float v2 = acc[mi][ni][2] + b0, v3 = acc[mi][ni][3] + b1;
            if (ACT) { v0 = gelu_f(v0); v1 = gelu_f(v1); v2 = gelu_f(v2); v3 = gelu_f(v3); }
            if (ROUT) { v0 = tf32_rna(v0); v1 = tf32_rna(v1); v2 = tf32_rna(v2); v3 = tf32_rna(v3); }
            size_t o0 = (size_t)r0 * N + cb;
            size_t o1 = (size_t)(r0 + 8) * N + cb;
            if (BETA) {
                float2 x0 = *(const float2*)&Cm[o0];
                float2 x1 = *(const float2*)&Cm[o1];
                v0 += x0.x; v1 += x0.y; v2 += x1.x; v3 += x1.y;
            }
            *(float2*)&Cm[o0] = make_float2(v0, v1);
            *(float2*)&Cm[o1] = make_float2(v2, v3);
        }
    }
}

// ---------------- weight transpose + tf32 pre-round: [K,N] -> [N,K] ----------------
__global__ void transpose_w(const float* __restrict__ src, float* __restrict__ dst,
                            int K, int N)
{
    int idx = blockIdx.x * blockDim.x + threadIdx.x;
    if (idx >= K * N) return;
    int k = idx / N, n = idx % N;
    dst[(size_t)n * K + k] = tf32_rna(src[idx]);
}

// ---------------- tf32 pre-round copy ----------------
__global__ void round_copy(const float* __restrict__ src, float* __restrict__ dst, int n4)
{
    int idx = blockIdx.x * blockDim.x + threadIdx.x;
    if (idx >= n4) return;
    float4 v = ((const float4*)src)[idx];
    v.x = tf32_rna(v.x); v.y = tf32_rna(v.y);
    v.z = tf32_rna(v.z); v.w = tf32_rna(v.w);
    ((float4*)dst)[idx] = v;
}

// ---------------- warp-per-token LayerNorm ----------------
// mode: 0 flat, 1 window partition, 2 window partition + roll; rnd: round dst to tf32
__global__ __launch_bounds__(256)
void ln2_kernel(const float* __restrict__ src, float* __restrict__ dst,
                const float* __restrict__ g, const float* __restrict__ b, int mode, int rnd)
{
    const int lane = threadIdx.x & 31;
    const int tok = blockIdx.x * 8 + (threadIdx.x >> 5);
    int spos;
    if (mode == 0) {
        spos = tok;
    } else {
        int n = tok & 127, wi = (tok >> 7) & 255, bb = tok >> 15;
        int zw = wi >> 4, hw = (wi >> 2) & 3, ww = wi & 3;
        int z = zw * 2 + (n >> 6), h = hw * 8 + ((n >> 3) & 7), w = ww * 8 + (n & 7);
        if (mode == 2) { z = (z + 1) & 31; h = (h + 4) & 31; w = (w + 4) & 31; }
        spos = ((bb * 32 + z) * 32 + h) * 32 + w;
    }
    const float* sp = src + (size_t)spos * C;
    float v[6]; float s = 0.f, s2 = 0.f;
#pragma unroll
    for (int j = 0; j < 6; j++) { v[j] = sp[lane + 32*j]; s += v[j]; s2 += v[j]*v[j]; }
#pragma unroll
    for (int o = 16; o > 0; o >>= 1) {
        s  += __shfl_xor_sync(0xffffffffu, s,  o);
        s2 += __shfl_xor_sync(0xffffffffu, s2, o);
    }
    float m = s * (1.0f/192.0f);
    float rstd = rsqrtf(s2 * (1.0f/192.0f) - m*m + 1e-5f);
    float* dp = dst + (size_t)tok * C;
#pragma unroll
    for (int j = 0; j < 6; j++) {
        int c = lane + 32*j;
        float o2 = (v[j] - m) * rstd * g[c] + b[c];
        dp[c] = rnd ? tf32_rna(o2) : o2;
    }
}

// ---------------- fused window-merge + residual add + LayerNorm (dst rounded) ----------------
__global__ __launch_bounds__(256)
void lnfuse_kernel(float* __restrict__ e, const float* __restrict__ wwin,
                   float* __restrict__ dst,
                   const float* __restrict__ g, const float* __restrict__ b, int shifted)
{
    const int lane = threadIdx.x & 31;
    const int pos = blockIdx.x * 8 + (threadIdx.x >> 5);
    int ww2 = pos & 31, hh = (pos >> 5) & 31, z = (pos >> 10) & 31, bb = pos >> 15;
    int sz = shifted ? 1 : 0, s4 = shifted ? 4 : 0;
    int z2 = (z - sz) & 31, h2 = (hh - s4) & 31, w2 = (ww2 - s4) & 31;
    int wi = ((z2 >> 1) << 4) | ((h2 >> 3) << 2) | (w2 >> 3);
    int n  = ((z2 & 1) << 6) | ((h2 & 7) << 3) | (w2 & 7);
    int tok = (bb * 256 + wi) * 128 + n;

    float* ep = e + (size_t)pos * C;
    const float* wp = wwin + (size_t)tok * C;
    float v[6]; float s = 0.f, s2 = 0.f;
#pragma unroll
    for (int j = 0; j < 6; j++) {
        int c = lane + 32*j;
        float a = ep[c] + wp[c];
        ep[c] = a;
        v[j] = a; s += a; s2 += a*a;
    }
#pragma unroll
    for (int o = 16; o > 0; o >>= 1) {
        s  += __shfl_xor_sync(0xffffffffu, s,  o);
        s2 += __shfl_xor_sync(0xffffffffu, s2, o);
    }
    float m = s * (1.0f/192.0f);
    float rstd = rsqrtf(s2 * (1.0f/192.0f) - m*m + 1e-5f);
    float* dp = dst + (size_t)pos * C;
#pragma unroll
    for (int j = 0; j < 6; j++) {
        int c = lane + 32*j;
        dp[c] = tf32_rna((v[j] - m) * rstd * g[c] + b[c]);
    }
}

// ---------------- register-tiled window attention (f32x2; output pre-rounded) ----------------
#define OQ 0
#define OK_ 4224
#define OV 8448
#define OS 13056
#define ORP 29952
#define ORID 30628
#define ATTN_SMEM_F 30756

__global__ __launch_bounds__(256)
void attn2_kernel(const float* __restrict__ rpb, int shifted)
{
    extern __shared__ float sm[];
    float* Qt = sm + OQ;
    float* Kt = sm + OK_;
    float* Vs = sm + OV;
    float* Ss = sm + OS;
    float* rpb_s = sm + ORP;
    int* rid_s = (int*)(sm + ORID);

    const int win = blockIdx.x;
    const int hh  = blockIdx.y;
    const int t = threadIdx.x;
    const int tx = t & 15, ty = t >> 4;
    const float scale = 0.1767766952966369f;

    for (int e = t; e < 4096; e += 256) {
        int n = e >> 5, d = e & 31;
        size_t base = ((size_t)(win * 128 + n)) * (3 * C) + hh * 32 + d;
        Qt[d * 132 + n] = g_qkv[base] * scale;
        Kt[d * 132 + n] = g_qkv[base + C];
        Vs[n * 36 + d]  = g_qkv[base + 2 * C];
    }
    for (int e = t; e < TBL; e += 256) rpb_s[e] = rpb[e * HEADS + hh];
    int wloc = win & 255;
    int zw = wloc >> 4, hw = (wloc >> 2) & 3, ww = wloc & 3;
    if (shifted && t < 128) {
        int z = zw * 2 + (t >> 6), h = hw * 8 + ((t >> 3) & 7), w = ww * 8 + (t & 7);
        rid_s[t] = (z < 30 ? 0 : (z < 31 ? 1 : 2)) * 9
                 + (h < 24 ? 0 : (h < 28 ? 1 : 2)) * 3
                 + (w < 24 ? 0 : (w < 28 ? 1 : 2));
    }
    __syncthreads();

    ull acc[8][4];
#pragma unroll
    for (int r = 0; r < 8; r++)
#pragma unroll
        for (int j = 0; j < 4; j++) acc[r][j] = 0ull;
#pragma unroll 4
    for (int d = 0; d < 32; d++) {
        float4 q0 = *(const float4*)&Qt[d*132 + ty*4];
        float4 q1 = *(const float4*)&Qt[d*132 + 64 + ty*4];
        ulonglong2 k01 = *(const ulonglong2*)&Kt[d*132 + tx*4];
        ulonglong2 k23 = *(const ulonglong2*)&Kt[d*132 + 64 + tx*4];
        ull kp[4] = {k01.x, k01.y, k23.x, k23.y};
        float qf[8] = {q0.x, q0.y, q0.z, q0.w, q1.x, q1.y, q1.z, q1.w};
#pragma unroll
        for (int r = 0; r < 8; r++) {
            ull qd = dup2(qf[r]);
#pragma unroll
            for (int j = 0; j < 4; j++) fma2(acc[r][j], qd, kp[j]);
        }
    }
#pragma unroll
    for (int rr = 0; rr < 8; rr++) {
        int n = (rr < 4 ? ty*4 + rr : 64 + ty*4 + rr - 4);
        int zn = n >> 6, hn = (n >> 3) & 7, wn = n & 7;
        int ridn = shifted ? rid_s[n] : 0;
#pragma unroll
        for (int j = 0; j < 4; j++) {
            float2 v = unpack2(acc[rr][j]);
            int mb = (j < 2 ? tx*4 + 2*j : 64 + tx*4 + 2*(j - 2));
            {
                int m = mb;
                int zm = m >> 6, hm = (m >> 3) & 7, wm = m & 7;
                int idx = (zn - zm + 1) * 225 + (hn - hm + 7) * 15 + (wn - wm + 7);
                v.x += rpb_s[idx];
                if (shifted && rid_s[m] != ridn) v.x -= 100.0f;
            }
            {
                int m = mb + 1;
                int zm = m >> 6, hm = (m >> 3) & 7, wm = m & 7;
                int idx = (zn - zm + 1) * 225 + (hn - hm + 7) * 15 + (wn - wm + 7);
                v.y += rpb_s[idx];
                if (shifted && rid_s[m] != ridn) v.y -= 100.0f;
            }
            *(float2*)&Ss[n * 132 + mb] = v;
        }
    }
    __syncthreads();

    {
        int n = t >> 1, half = t & 1;
        float* row = &Ss[n * 132 + half * 64];
        float mx = -1e30f;
#pragma unroll
        for (int j = 0; j < 16; j++) {
            float4 v = *(const float4*)&row[j * 4];
            mx = fmaxf(mx, fmaxf(fmaxf(v.x, v.y), fmaxf(v.z, v.w)));
        }
        mx = fmaxf(mx, __shfl_xor_sync(0xffffffffu, mx, 1));
        float sum = 0.f;
#pragma unroll
        for (int j = 0; j < 16; j++) {
            float4 v = *(float4*)&row[j * 4];
            v.x = __expf(v.x - mx); v.y = __expf(v.y - mx);
            v.z = __expf(v.z - mx); v.w = __expf(v.w - mx);
            sum += v.x + v.y + v.z + v.w;
            *(float4*)&row[j * 4] = v;
        }
        sum += __shfl_xor_sync(0xffffffffu, sum, 1);
        float inv = 1.0f / sum;
#pragma unroll
        for (int j = 0; j < 16; j++) {
            float4 v = *(float4*)&row[j * 4];
            v.x *= inv; v.y *= inv; v.z *= inv; v.w *= inv;
            *(float4*)&row[j * 4] = v;
        }
    }
    __syncthreads();

    {
        int r0 = (t >> 2) * 2;
        int d0 = (t & 3) * 8;
        ull av[2][4];
#pragma unroll
        for (int i = 0; i < 2; i++)
#pragma unroll
            for (int j = 0; j < 4; j++) av[i][j] = 0ull;
#pragma unroll 8
        for (int m = 0; m < 128; m++) {
            float s0 = Ss[r0 * 132 + m];
            float s1 = Ss[(r0 + 1) * 132 + m];
            ulonglong2 v01 = *(const ulonglong2*)&Vs[m * 36 + d0];
            ulonglong2 v23 = *(const ulonglong2*)&Vs[m * 36 + d0 + 4];
            ull sd0 = dup2(s0), sd1 = dup2(s1);
            fma2(av[0][0], sd0, v01.x); fma2(av[0][1], sd0, v01.y);
            fma2(av[0][2], sd0, v23.x); fma2(av[0][3], sd0, v23.y);
            fma2(av[1][0], sd1, v01.x); fma2(av[1][1], sd1, v01.y);
            fma2(av[1][2], sd1, v23.x); fma2(av[1][3], sd1, v23.y);
        }
#pragma unroll
        for (int i = 0; i < 2; i++) {
            float of[8];
#pragma unroll
            for (int j = 0; j < 4; j++) {
                float2 v = unpack2(av[i][j]);
                of[2*j] = tf32_rna(v.x); of[2*j+1] = tf32_rna(v.y);
            }
            size_t ob = ((size_t)(win * 128 + r0 + i)) * C + hh * 32 + d0;
            *(float4*)&g_o[ob]     = make_float4(of[0], of[1], of[2], of[3]);
            *(float4*)&g_o[ob + 4] = make_float4(of[4], of[5], of[6], of[7]);
        }
    }
}

// ---------------- patch-embed gather (rounded) / recon scatter ----------------
__global__ void gather_kernel(const float* __restrict__ x, float* __restrict__ xg)
{
    int idx = blockIdx.x * blockDim.x + threadIdx.x;
    if (idx >= NPOS * 128) return;
    int t = idx & 127, pos = idx >> 7;
    int w = pos & 31, h = (pos >> 5) & 31, z = (pos >> 10) & 31, b = pos >> 15;
    int c4 = t >> 5, i = (t >> 4) & 1, j = (t >> 2) & 3, k = t & 3;
    xg[idx] = tf32_rna(x[((((size_t)b * 4 + c4) * 64 + 2 * z + i) * 128 + 4 * h + j) * 128 + 4 * w + k]);
}

__global__ void scatter_kernel(const float* __restrict__ rec, const float* __restrict__ rec_b,
                               float* __restrict__ out)
{
    int idx = blockIdx.x * blockDim.x + threadIdx.x;
    if (idx >= NPOS * 128) return;
    int t = idx & 127, pos = idx >> 7;
    int w = pos & 31, h = (pos >> 5) & 31, z = (pos >> 10) & 31, b = pos >> 15;
    int o = t >> 5, i = (t >> 4) & 1, j = (t >> 2) & 3, k = t & 3;
    out[((((size_t)b * 4 + o) * 64 + 2 * z + i) * 128 + 4 * h + j) * 128 + 4 * w + k]
        = rec[idx] + rec_b[o];
}

// ---------------- host launcher ----------------
extern "C" void kernel_launch(void* const* d_in, const int* in_sizes, int n_in,
                              void* d_out, int out_size)
{
    const float* x       = (const float*)d_in[0];
    const float* pe_w    = (const float*)d_in[1];
    const float* pe_b    = (const float*)d_in[2];
    const float* pe_ln_g = (const float*)d_in[3];
    const float* pe_ln_b = (const float*)d_in[4];
    const float* ln1_g   = (const float*)d_in[5];
    const float* ln1_b   = (const float*)d_in[6];
    const float* qkv_w   = (const float*)d_in[7];
    const float* qkv_b   = (const float*)d_in[8];
    const float* proj_w  = (const float*)d_in[9];
    const float* proj_b  = (const float*)d_in[10];
    const float* rpb     = (const float*)d_in[11];
    const float* ln2_g   = (const float*)d_in[12];
    const float* ln2_b   = (const float*)d_in[13];
    const float* fc1_w   = (const float*)d_in[14];
    const float* fc1_b   = (const float*)d_in[15];
    const float* fc2_w   = (const float*)d_in[16];
    const float* fc2_b   = (const float*)d_in[17];
    const float* rec_w   = (const float*)d_in[18];
    const float* rec_b   = (const float*)d_in[19];
    float* out = (float*)d_out;

    float *e, *w, *qkv, *h, *o, *wt, *zeros;
    cudaGetSymbolAddress((void**)&e,     g_e);
    cudaGetSymbolAddress((void**)&w,     g_w);
    cudaGetSymbolAddress((void**)&qkv,   g_qkv);
    cudaGetSymbolAddress((void**)&h,     g_h);
    cudaGetSymbolAddress((void**)&o,     g_o);
    cudaGetSymbolAddress((void**)&wt,    g_wt);
    cudaGetSymbolAddress((void**)&zeros, g_zeros);

    const int ATTN_SMEM = ATTN_SMEM_F * (int)sizeof(float);
    cudaFuncSetAttribute(attn2_kernel, cudaFuncAttributeMaxDynamicSharedMemorySize, ATTN_SMEM);

    // ---- weight transposes + pre-round ([K,N] -> [N,K]) ----
    for (int d = 0; d < DEPTH; d++) {
        transpose_w<<<(192*576 + 255)/256, 256>>>(qkv_w + (size_t)d*192*576, wt + QO  + (size_t)d*110592, 192, 576);
        transpose_w<<<(192*192 + 255)/256, 256>>>(proj_w + (size_t)d*192*192, wt + PO  + (size_t)d*36864, 192, 192);
        transpose_w<<<(192*768 + 255)/256, 256>>>(fc1_w + (size_t)d*192*768, wt + F1O + (size_t)d*147456, 192, 768);
        transpose_w<<<(768*192 + 255)/256, 256>>>(fc2_w + (size_t)d*768*192, wt + F2O + (size_t)d*147456, 768, 192);
    }
    transpose_w<<<(192*128 + 255)/256, 256>>>(rec_w, wt + RO, 192, 128);
    round_copy<<<(192*128/4 + 255)/256, 256>>>(pe_w, wt + PEO, 192*128/4);

    // ---- patch embed: gather(rounded) -> GEMM -> LN ----
    gather_kernel<<<(NPOS * 128) / 256, 256>>>(x, h);
    gemm_mma<0,0,0><<<dim3(3, NPOS/128), 128>>>(h, wt + PEO, pe_b, w, 192, 128);
    ln2_kernel<<<NPOS / 8, 256>>>(w, e, pe_ln_g, pe_ln_b, 0, 0);

    // ---- transformer layers ----
    for (int d = 0; d < DEPTH; d++) {
        int sh = d & 1;
        ln2_kernel<<<NPOS / 8, 256>>>(e, w, ln1_g + d * C, ln1_b + d * C, sh ? 2 : 1, 1);
        gemm_mma<0,0,0><<<dim3(9, NPOS/128), 128>>>(
            w, wt + QO + (size_t)d*110592, qkv_b + d * 3 * C, qkv, 3 * C, C);
        attn2_kernel<<<dim3(B * NW, HEADS), 256, ATTN_SMEM>>>(rpb + (size_t)d * TBL * HEADS, sh);
        gemm_mma<0,0,0><<<dim3(3, NPOS/128), 128>>>(
            o, wt + PO + (size_t)d*36864, proj_b + d * C, w, C, C);
        // fused: e += unwindow(w); qkv = round(LN2(e))
        lnfuse_kernel<<<NPOS / 8, 256>>>(e, w, qkv, ln2_g + d * C, ln2_b + d * C, sh);
        gemm_mma<1,0,1><<<dim3(12, NPOS/128), 128>>>(
            qkv, wt + F1O + (size_t)d*147456, fc1_b + d * 4 * C, h, 4 * C, C);
        gemm_mma<0,1,0><<<dim3(3, NPOS/128), 128>>>(
            h, wt + F2O + (size_t)d*147456, fc2_b + d * C, e, C, 4 * C);
    }

    // ---- reconstruction: round e -> GEMM -> scatter ----
    round_copy<<<(NPOS * C / 4) / 256, 256>>>(e, w, NPOS * C / 4);
    gemm_mma<0,0,0><<<dim3(2, NPOS/128), 128>>>(w, wt + RO, zeros, qkv, 128, C);
    scatter_kernel<<<(NPOS * 128) / 256, 256>>>(qkv, rec_b, out);
}

// round 11
// speedup vs baseline: 1.3830x; 1.1024x over previous
#include <cuda_runtime.h>
#include <math.h>
#include <stdint.h>

typedef unsigned long long ull;

// ---------------- problem constants ----------------
#define B 2
#define C 192
#define HEADS 6
#define ZP 32
#define NPOS (B*ZP*ZP*ZP)          // 65536
#define NW 256
#define DEPTH 4
#define TBL 675

// weight scratch offsets (floats)
#define QO 0
#define PO 442368
#define F1O 589824
#define F2O 1179648
#define RO 1769472
#define PEO 1794048
#define WT_TOTAL 1818624

// ---------------- scratch ----------------
__device__ float g_e  [(size_t)NPOS * C];
__device__ float g_w  [(size_t)NPOS * C];
__device__ float g_qkv[(size_t)NPOS * 3 * C];
__device__ float g_o  [(size_t)NPOS * C];
__device__ float g_h  [(size_t)NPOS * 4 * C];
__device__ float g_wt [WT_TOTAL];
__device__ float g_bias[DEPTH * HEADS * 128 * 128];   // rpb gathered per (d,h,n,m)
__device__ float g_zeros[192];

// ---------------- helpers ----------------
__device__ __forceinline__ float gelu_f(float v){
    return 0.5f * v * (1.0f + erff(v * 0.70710678118654752f));
}
__device__ __forceinline__ void fma2(ull &d, ull a, ull b){
    asm("fma.rn.f32x2 %0, %1, %2, %0;" : "+l"(d) : "l"(a), "l"(b));
}
__device__ __forceinline__ ull dup2(float x){
    ull r; asm("mov.b64 %0, {%1, %1};" : "=l"(r) : "f"(x)); return r;
}
__device__ __forceinline__ float2 unpack2(ull v){
    float2 f; asm("mov.b64 {%0, %1}, %2;" : "=f"(f.x), "=f"(f.y) : "l"(v)); return f;
}
__device__ __forceinline__ void mma_tf32(float* d, const uint32_t* a, const uint32_t* b){
    asm volatile(
        "mma.sync.aligned.m16n8k8.row.col.f32.tf32.tf32.f32 "
        "{%0,%1,%2,%3}, {%4,%5,%6,%7}, {%8,%9}, {%0,%1,%2,%3};"
        : "+f"(d[0]), "+f"(d[1]), "+f"(d[2]), "+f"(d[3])
        : "r"(a[0]), "r"(a[1]), "r"(a[2]), "r"(a[3]), "r"(b[0]), "r"(b[1]));
}
__device__ __forceinline__ float tf32_rna(float x){
    uint32_t r; asm("cvt.rna.tf32.f32 %0, %1;" : "=r"(r) : "f"(x));
    return __uint_as_float(r);
}
__device__ __forceinline__ uint32_t smem_u32(const void* p){
    uint32_t a;
    asm("{ .reg .u64 t; cvta.to.shared.u64 t, %1; cvt.u32.u64 %0, t; }" : "=r"(a) : "l"(p));
    return a;
}
__device__ __forceinline__ void cp16(uint32_t d, const void* s){
    asm volatile("cp.async.cg.shared.global [%0], [%1], 16;" :: "r"(d), "l"(s));
}
__device__ __forceinline__ void cp_commit(){
    asm volatile("cp.async.commit_group;");
}
template<int Npend>
__device__ __forceinline__ void cp_wait(){
    asm volatile("cp.async.wait_group %0;" :: "n"(Npend) : "memory");
}

// ================= fused setup: weight transposes + rounding + bias table =================
__global__ void setup_kernel(const float* __restrict__ qkv_w, const float* __restrict__ proj_w,
                             const float* __restrict__ fc1_w, const float* __restrict__ fc2_w,
                             const float* __restrict__ rec_w, const float* __restrict__ pe_w,
                             const float* __restrict__ rpb)
{
    int idx = blockIdx.x * 256 + threadIdx.x;
    if (idx < 442368) {                       // qkv [K=192,N=576] -> [N,K]
        int d = idx / 110592, r = idx % 110592;
        int k = r / 576, n = r % 576;
        g_wt[QO + d * 110592 + n * 192 + k] = tf32_rna(qkv_w[idx]);
        return;
    }
    idx -= 442368;
    if (idx < 147456) {                       // proj [192,192]
        int d = idx / 36864, r = idx % 36864;
        int k = r / 192, n = r % 192;
        g_wt[PO + d * 36864 + n * 192 + k] = tf32_rna(proj_w[idx]);
        return;
    }
    idx -= 147456;
    if (idx < 589824) {                       // fc1 [192,768]
        int d = idx / 147456, r = idx % 147456;
        int k = r / 768, n = r % 768;
        g_wt[F1O + d * 147456 + n * 192 + k] = tf32_rna(fc1_w[idx]);
        return;
    }
    idx -= 589824;
    if (idx < 589824) {                       // fc2 [768,192]
        int d = idx / 147456, r = idx % 147456;
        int k = r / 192, n = r % 192;
        g_wt[F2O + d * 147456 + n * 768 + k] = tf32_rna(fc2_w[idx]);
        return;
    }
    idx -= 589824;
    if (idx < 24576) {                        // rec [192,128]
        int k = idx / 128, n = idx % 128;
        g_wt[RO + n * 192 + k] = tf32_rna(rec_w[idx]);
        return;
    }
    idx -= 24576;
    if (idx < 24576) {                        // pe (already [N,K]) round only
        g_wt[PEO + idx] = tf32_rna(pe_w[idx]);
        return;
    }
    idx -= 24576;
    if (idx < DEPTH * HEADS * 16384) {        // bias[d][h][n][m]
        int d = idx / 98304, r = idx % 98304;
        int h = r >> 14, n = (r >> 7) & 127, m = r & 127;
        int zn = n >> 6, hn = (n >> 3) & 7, wn = n & 7;
        int zm = m >> 6, hm = (m >> 3) & 7, wm = m & 7;
        int bi = (zn - zm + 1) * 225 + (hn - hm + 7) * 15 + (wn - wm + 7);
        g_bias[idx] = rpb[((size_t)d * TBL + bi) * HEADS + h];
    }
}
#define SETUP_TOTAL (442368 + 147456 + 589824 + 589824 + 24576 + 24576 + DEPTH*HEADS*16384)

// ================= tf32 mma.sync GEMM (pre-rounded, cp.async, single sync) =================
#define ASZB (128 * 36 * 4)
#define BSZB (64 * 36 * 4)
template<int ACT, int BETA, int ROUT>
__global__ __launch_bounds__(128)
void gemm_mma(const float* __restrict__ A, const float* __restrict__ Bw,
              const float* __restrict__ bias, float* __restrict__ Cm,
              int N, int K)
{
    __shared__ float As[2][128 * 36];
    __shared__ float Bs[2][64 * 36];
    const int t = threadIdx.x;
    const int lane = t & 31, wid = t >> 5;
    const int warpM = wid * 32;
    const int g = lane >> 2, tg = lane & 3;
    const int bm = blockIdx.y << 7;
    const int bn = blockIdx.x << 6;
    const int K4 = K >> 2;
    const int nk = K >> 5;

    const float4* A4 = (const float4*)A;
    const float4* B4 = (const float4*)Bw;
    const int lrow = t >> 3;
    const int lk4  = t & 7;
    int aBase[8], aOff[8];
#pragma unroll
    for (int i = 0; i < 8; i++) {
        int row = lrow + i * 16;
        aBase[i] = (bm + row) * K4 + lk4;
        aOff[i] = (row * 36 + lk4 * 4) * 4;
    }
    int bBase[4], bOff[4];
#pragma unroll
    for (int i = 0; i < 4; i++) {
        int row = lrow + i * 16;
        bBase[i] = (bn + row) * K4 + lk4;
        bOff[i] = (row * 36 + lk4 * 4) * 4;
    }
    const uint32_t uA = smem_u32(&As[0][0]);
    const uint32_t uB = smem_u32(&Bs[0][0]);

#pragma unroll
    for (int i = 0; i < 8; i++) cp16(uA + aOff[i], &A4[aBase[i]]);
#pragma unroll
    for (int i = 0; i < 4; i++) cp16(uB + bOff[i], &B4[bBase[i]]);
    cp_commit();

    float acc[2][8][4];
#pragma unroll
    for (int mi = 0; mi < 2; mi++)
#pragma unroll
        for (int ni = 0; ni < 8; ni++)
#pragma unroll
            for (int j = 0; j < 4; j++) acc[mi][ni][j] = 0.f;

    for (int kt = 0; kt < nk; kt++) {
        cp_wait<0>();
        __syncthreads();
        const int buf = kt & 1;
        if (kt + 1 < nk) {               // issue next tile; readers of buf^1 passed the sync
            const int nb = buf ^ 1;
            const int ko = (kt + 1) * 8;
#pragma unroll
            for (int i = 0; i < 8; i++) cp16(uA + nb * ASZB + aOff[i], &A4[aBase[i] + ko]);
#pragma unroll
            for (int i = 0; i < 4; i++) cp16(uB + nb * BSZB + bOff[i], &B4[bBase[i] + ko]);
            cp_commit();
        }
        const uint32_t* Asu = (const uint32_t*)As[buf];
        const uint32_t* Bsu = (const uint32_t*)Bs[buf];
#pragma unroll
        for (int ks = 0; ks < 4; ks++) {
            const int k0 = ks * 8;
            uint32_t af[2][4];
#pragma unroll
            for (int mi = 0; mi < 2; mi++) {
                int r = (warpM + mi * 16 + g) * 36 + k0 + tg;
                af[mi][0] = Asu[r];
                af[mi][1] = Asu[r + 8 * 36];
                af[mi][2] = Asu[r + 4];
                af[mi][3] = Asu[r + 8 * 36 + 4];
            }
#pragma unroll
            for (int ni = 0; ni < 8; ni++) {
                uint32_t bf[2];
                int r = (ni * 8 + g) * 36 + k0 + tg;
                bf[0] = Bsu[r];
                bf[1] = Bsu[r + 4];
                mma_tf32(acc[0][ni], af[0], bf);
                mma_tf32(acc[1][ni], af[1], bf);
            }
        }
        __syncthreads();
    }

#pragma unroll
    for (int mi = 0; mi < 2; mi++) {
        int r0 = bm + warpM + mi * 16 + g;
#pragma unroll
        for (int ni = 0; ni < 8; ni++) {
            int cb = bn + ni * 8 + 2 * tg;
            float b0 = bias[cb], b1 = bias[cb + 1];
            float v0 = acc[mi][ni][0] + b0, v1 = acc[mi][ni][1] + b1;
            float v2 = acc[mi][ni][2] + b0, v3 = acc[mi][ni][3] + b1;
            if (ACT) { v0 = gelu_f(v0); v1 = gelu_f(v1); v2 = gelu_f(v2); v3 = gelu_f(v3); }
            if (ROUT) { v0 = tf32_rna(v0); v1 = tf32_rna(v1); v2 = tf32_rna(v2); v3 = tf32_rna(v3); }
            size_t o0 = (size_t)r0 * N + cb;
            size_t o1 = (size_t)(r0 + 8) * N + cb;
            if (BETA) {
                float2 x0 = *(const float2*)&Cm[o0];
                float2 x1 = *(const float2*)&Cm[o1];
                v0 += x0.x; v1 += x0.y; v2 += x1.x; v3 += x1.y;
            }
            *(float2*)&Cm[o0] = make_float2(v0, v1);
            *(float2*)&Cm[o1] = make_float2(v2, v3);
        }
    }
}

// ---------------- tf32 pre-round copy ----------------
__global__ void round_copy(const float* __restrict__ src, float* __restrict__ dst, int n4)
{
    int idx = blockIdx.x * blockDim.x + threadIdx.x;
    if (idx >= n4) return;
    float4 v = ((const float4*)src)[idx];
    v.x = tf32_rna(v.x); v.y = tf32_rna(v.y);
    v.z = tf32_rna(v.z); v.w = tf32_rna(v.w);
    ((float4*)dst)[idx] = v;
}

// ---------------- warp-per-token LayerNorm ----------------
__global__ __launch_bounds__(256)
void ln2_kernel(const float* __restrict__ src, float* __restrict__ dst,
                const float* __restrict__ g, const float* __restrict__ b, int mode, int rnd)
{
    const int lane = threadIdx.x & 31;
    const int tok = blockIdx.x * 8 + (threadIdx.x >> 5);
    int spos;
    if (mode == 0) {
        spos = tok;
    } else {
        int n = tok & 127, wi = (tok >> 7) & 255, bb = tok >> 15;
        int zw = wi >> 4, hw = (wi >> 2) & 3, ww = wi & 3;
        int z = zw * 2 + (n >> 6), h = hw * 8 + ((n >> 3) & 7), w = ww * 8 + (n & 7);
        if (mode == 2) { z = (z + 1) & 31; h = (h + 4) & 31; w = (w + 4) & 31; }
        spos = ((bb * 32 + z) * 32 + h) * 32 + w;
    }
    const float* sp = src + (size_t)spos * C;
    float v[6]; float s = 0.f, s2 = 0.f;
#pragma unroll
    for (int j = 0; j < 6; j++) { v[j] = sp[lane + 32*j]; s += v[j]; s2 += v[j]*v[j]; }
#pragma unroll
    for (int o = 16; o > 0; o >>= 1) {
        s  += __shfl_xor_sync(0xffffffffu, s,  o);
        s2 += __shfl_xor_sync(0xffffffffu, s2, o);
    }
    float m = s * (1.0f/192.0f);
    float rstd = rsqrtf(s2 * (1.0f/192.0f) - m*m + 1e-5f);
    float* dp = dst + (size_t)tok * C;
#pragma unroll
    for (int j = 0; j < 6; j++) {
        int c = lane + 32*j;
        float o2 = (v[j] - m) * rstd * g[c] + b[c];
        dp[c] = rnd ? tf32_rna(o2) : o2;
    }
}

// ---------------- fused window-merge + residual add + LayerNorm (dst rounded) ----------------
__global__ __launch_bounds__(256)
void lnfuse_kernel(float* __restrict__ e, const float* __restrict__ wwin,
                   float* __restrict__ dst,
                   const float* __restrict__ g, const float* __restrict__ b, int shifted)
{
    const int lane = threadIdx.x & 31;
    const int pos = blockIdx.x * 8 + (threadIdx.x >> 5);
    int ww2 = pos & 31, hh = (pos >> 5) & 31, z = (pos >> 10) & 31, bb = pos >> 15;
    int sz = shifted ? 1 : 0, s4 = shifted ? 4 : 0;
    int z2 = (z - sz) & 31, h2 = (hh - s4) & 31, w2 = (ww2 - s4) & 31;
    int wi = ((z2 >> 1) << 4) | ((h2 >> 3) << 2) | (w2 >> 3);
    int n  = ((z2 & 1) << 6) | ((h2 & 7) << 3) | (w2 & 7);
    int tok = (bb * 256 + wi) * 128 + n;

    float* ep = e + (size_t)pos * C;
    const float* wp = wwin + (size_t)tok * C;
    float v[6]; float s = 0.f, s2 = 0.f;
#pragma unroll
    for (int j = 0; j < 6; j++) {
        int c = lane + 32*j;
        float a = ep[c] + wp[c];
        ep[c] = a;
        v[j] = a; s += a; s2 += a*a;
    }
#pragma unroll
    for (int o = 16; o > 0; o >>= 1) {
        s  += __shfl_xor_sync(0xffffffffu, s,  o);
        s2 += __shfl_xor_sync(0xffffffffu, s2, o);
    }
    float m = s * (1.0f/192.0f);
    float rstd = rsqrtf(s2 * (1.0f/192.0f) - m*m + 1e-5f);
    float* dp = dst + (size_t)pos * C;
#pragma unroll
    for (int j = 0; j < 6; j++) {
        int c = lane + 32*j;
        dp[c] = tf32_rna((v[j] - m) * rstd * g[c] + b[c]);
    }
}

// ---------------- window attention: f32x2 QK^T + bias table + tf32 MMA AV ----------------
#define OQ 0
#define OK_ 4224
#define OV 8448
#define OS 12672
#define ORID 29568
#define ATTN_SMEM_F 29704

__global__ __launch_bounds__(256)
void attn2_kernel(const float* __restrict__ biasT, int shifted)
{
    extern __shared__ float sm[];
    float* Qt = sm + OQ;          // [32][132] d-major
    float* Kt = sm + OK_;         // [32][132] d-major
    float* Vt = sm + OV;          // [32][132] d-major (tf32-rounded)
    float* Ss = sm + OS;          // [128][132]
    int* rid_s = (int*)(sm + ORID);

    const int win = blockIdx.x;
    const int hh  = blockIdx.y;
    const int t = threadIdx.x;
    const int lane = t & 31, wid = t >> 5;
    const int g = lane >> 2, tg = lane & 3;
    const int tx = t & 15, ty = t >> 4;
    const float scale = 0.1767766952966369f;
    const float* bl = biasT + (size_t)hh * 16384;

    for (int e = t; e < 4096; e += 256) {
        int n = e >> 5, d = e & 31;
        size_t base = ((size_t)(win * 128 + n)) * (3 * C) + hh * 32 + d;
        Qt[d * 132 + n] = g_qkv[base] * scale;
        Kt[d * 132 + n] = g_qkv[base + C];
        Vt[d * 132 + n] = tf32_rna(g_qkv[base + 2 * C]);
    }
    int wloc = win & 255;
    int zw = wloc >> 4, hw = (wloc >> 2) & 3, ww = wloc & 3;
    if (shifted && t < 128) {
        int z = zw * 2 + (t >> 6), h = hw * 8 + ((t >> 3) & 7), w = ww * 8 + (t & 7);
        rid_s[t] = (z < 30 ? 0 : (z < 31 ? 1 : 2)) * 9
                 + (h < 24 ? 0 : (h < 28 ? 1 : 2)) * 3
                 + (w < 24 ? 0 : (w < 28 ? 1 : 2));
    }
    __syncthreads();

    // ---- QK^T (f32x2, fp32 precision) ----
    ull acc[8][4];
#pragma unroll
    for (int r = 0; r < 8; r++)
#pragma unroll
        for (int j = 0; j < 4; j++) acc[r][j] = 0ull;
#pragma unroll 4
    for (int d = 0; d < 32; d++) {
        float4 q0 = *(const float4*)&Qt[d*132 + ty*4];
        float4 q1 = *(const float4*)&Qt[d*132 + 64 + ty*4];
        ulonglong2 k01 = *(const ulonglong2*)&Kt[d*132 + tx*4];
        ulonglong2 k23 = *(const ulonglong2*)&Kt[d*132 + 64 + tx*4];
        ull kp[4] = {k01.x, k01.y, k23.x, k23.y};
        float qf[8] = {q0.x, q0.y, q0.z, q0.w, q1.x, q1.y, q1.z, q1.w};
#pragma unroll
        for (int r = 0; r < 8; r++) {
            ull qd = dup2(qf[r]);
#pragma unroll
            for (int j = 0; j < 4; j++) fma2(acc[r][j], qd, kp[j]);
        }
    }
#pragma unroll
    for (int rr = 0; rr < 8; rr++) {
        int n = (rr < 4 ? ty*4 + rr : 64 + ty*4 + rr - 4);
        int ridn = shifted ? rid_s[n] : 0;
        const float* brow = bl + n * 128;
#pragma unroll
        for (int j = 0; j < 4; j++) {
            float2 v = unpack2(acc[rr][j]);
            int mb = (j < 2 ? tx*4 + 2*j : 64 + tx*4 + 2*(j - 2));
            float2 bv = *(const float2*)&brow[mb];
            v.x += bv.x; v.y += bv.y;
            if (shifted) {
                if (rid_s[mb]     != ridn) v.x -= 100.0f;
                if (rid_s[mb + 1] != ridn) v.y -= 100.0f;
            }
            *(float2*)&Ss[n * 132 + mb] = v;
        }
    }
    __syncthreads();

    // ---- softmax (rounds P to tf32 for the AV MMA) ----
    {
        int n = t >> 1, half = t & 1;
        float* row = &Ss[n * 132 + half * 64];
        float mx = -1e30f;
#pragma unroll
        for (int j = 0; j < 16; j++) {
            float4 v = *(const float4*)&row[j * 4];
            mx = fmaxf(mx, fmaxf(fmaxf(v.x, v.y), fmaxf(v.z, v.w)));
        }
        mx = fmaxf(mx, __shfl_xor_sync(0xffffffffu, mx, 1));
        float sum = 0.f;
#pragma unroll
        for (int j = 0; j < 16; j++) {
            float4 v = *(float4*)&row[j * 4];
            v.x = __expf(v.x - mx); v.y = __expf(v.y - mx);
            v.z = __expf(v.z - mx); v.w = __expf(v.w - mx);
            sum += v.x + v.y + v.z + v.w;
            *(float4*)&row[j * 4] = v;
        }
        sum += __shfl_xor_sync(0xffffffffu, sum, 1);
        float inv = 1.0f / sum;
#pragma unroll
        for (int j = 0; j < 16; j++) {
            float4 v = *(float4*)&row[j * 4];
            v.x = tf32_rna(v.x * inv); v.y = tf32_rna(v.y * inv);
            v.z = tf32_rna(v.z * inv); v.w = tf32_rna(v.w * inv);
            *(float4*)&row[j * 4] = v;
        }
    }
    __syncthreads();

    // ---- A @ V via tf32 mma: warp w -> rows [16w,16w+16), full d=32 ----
    {
        float av[4][4];
#pragma unroll
        for (int ni = 0; ni < 4; ni++)
#pragma unroll
            for (int j = 0; j < 4; j++) av[ni][j] = 0.f;
        const uint32_t* Ps = (const uint32_t*)Ss;
        const uint32_t* Vu = (const uint32_t*)Vt;
#pragma unroll
        for (int ks = 0; ks < 16; ks++) {
            const int k0 = ks * 8;
            uint32_t af[4];
            int ra = (wid * 16 + g) * 132 + k0 + tg;
            af[0] = Ps[ra];
            af[1] = Ps[ra + 8 * 132];
            af[2] = Ps[ra + 4];
            af[3] = Ps[ra + 8 * 132 + 4];
#pragma unroll
            for (int ni = 0; ni < 4; ni++) {
                uint32_t bf[2];
                int rb = (ni * 8 + g) * 132 + k0 + tg;
                bf[0] = Vu[rb];
                bf[1] = Vu[rb + 4];
                mma_tf32(av[ni], af, bf);
            }
        }
#pragma unroll
        for (int ni = 0; ni < 4; ni++) {
            int n0 = wid * 16 + g;
            int d = ni * 8 + 2 * tg;
            size_t o0 = ((size_t)(win * 128 + n0)) * C + hh * 32 + d;
            size_t o1 = ((size_t)(win * 128 + n0 + 8)) * C + hh * 32 + d;
            *(float2*)&g_o[o0] = make_float2(tf32_rna(av[ni][0]), tf32_rna(av[ni][1]));
            *(float2*)&g_o[o1] = make_float2(tf32_rna(av[ni][2]), tf32_rna(av[ni][3]));
        }
    }
}

// ---------------- patch-embed gather (rounded) / recon scatter ----------------
__global__ void gather_kernel(const float* __restrict__ x, float* __restrict__ xg)
{
    int idx = blockIdx.x * blockDim.x + threadIdx.x;
    if (idx >= NPOS * 128) return;
    int t = idx & 127, pos = idx >> 7;
    int w = pos & 31, h = (pos >> 5) & 31, z = (pos >> 10) & 31, b = pos >> 15;
    int c4 = t >> 5, i = (t >> 4) & 1, j = (t >> 2) & 3, k = t & 3;
    xg[idx] = tf32_rna(x[((((size_t)b * 4 + c4) * 64 + 2 * z + i) * 128 + 4 * h + j) * 128 + 4 * w + k]);
}

__global__ void scatter_kernel(const float* __restrict__ rec, const float* __restrict__ rec_b,
                               float* __restrict__ out)
{
    int idx = blockIdx.x * blockDim.x + threadIdx.x;
    if (idx >= NPOS * 128) return;
    int t = idx & 127, pos = idx >> 7;
    int w = pos & 31, h = (pos >> 5) & 31, z = (pos >> 10) & 31, b = pos >> 15;
    int o = t >> 5, i = (t >> 4) & 1, j = (t >> 2) & 3, k = t & 3;
    out[((((size_t)b * 4 + o) * 64 + 2 * z + i) * 128 + 4 * h + j) * 128 + 4 * w + k]
        = rec[idx] + rec_b[o];
}

// ---------------- host launcher ----------------
extern "C" void kernel_launch(void* const* d_in, const int* in_sizes, int n_in,
                              void* d_out, int out_size)
{
    const float* x       = (const float*)d_in[0];
    const float* pe_w    = (const float*)d_in[1];
    const float* pe_b    = (const float*)d_in[2];
    const float* pe_ln_g = (const float*)d_in[3];
    const float* pe_ln_b = (const float*)d_in[4];
    const float* ln1_g   = (const float*)d_in[5];
    const float* ln1_b   = (const float*)d_in[6];
    const float* qkv_w   = (const float*)d_in[7];
    const float* qkv_b   = (const float*)d_in[8];
    const float* proj_w  = (const float*)d_in[9];
    const float* proj_b  = (const float*)d_in[10];
    const float* rpb     = (const float*)d_in[11];
    const float* ln2_g   = (const float*)d_in[12];
    const float* ln2_b   = (const float*)d_in[13];
    const float* fc1_w   = (const float*)d_in[14];
    const float* fc1_b   = (const float*)d_in[15];
    const float* fc2_w   = (const float*)d_in[16];
    const float* fc2_b   = (const float*)d_in[17];
    const float* rec_w   = (const float*)d_in[18];
    const float* rec_b   = (const float*)d_in[19];
    float* out = (float*)d_out;

    float *e, *w, *qkv, *h, *o, *wt, *bias, *zeros;
    cudaGetSymbolAddress((void**)&e,     g_e);
    cudaGetSymbolAddress((void**)&w,     g_w);
    cudaGetSymbolAddress((void**)&qkv,   g_qkv);
    cudaGetSymbolAddress((void**)&h,     g_h);
    cudaGetSymbolAddress((void**)&o,     g_o);
    cudaGetSymbolAddress((void**)&wt,    g_wt);
    cudaGetSymbolAddress((void**)&bias,  g_bias);
    cudaGetSymbolAddress((void**)&zeros, g_zeros);

    const int ATTN_SMEM = ATTN_SMEM_F * (int)sizeof(float);
    cudaFuncSetAttribute(attn2_kernel, cudaFuncAttributeMaxDynamicSharedMemorySize, ATTN_SMEM);

    // (0) fused setup
    setup_kernel<<<(SETUP_TOTAL + 255) / 256, 256>>>(qkv_w, proj_w, fc1_w, fc2_w, rec_w, pe_w, rpb);

    // (1..3) patch embed
    gather_kernel<<<(NPOS * 128) / 256, 256>>>(x, h);
    gemm_mma<0,0,0><<<dim3(3, NPOS/128), 128>>>(h, wt + PEO, pe_b, w, 192, 128);
    ln2_kernel<<<NPOS / 8, 256>>>(w, e, pe_ln_g, pe_ln_b, 0, 0);

    // ---- transformer layers ----
    for (int d = 0; d < DEPTH; d++) {
        int sh = d & 1;
        ln2_kernel<<<NPOS / 8, 256>>>(e, w, ln1_g + d * C, ln1_b + d * C, sh ? 2 : 1, 1);
        gemm_mma<0,0,0><<<dim3(9, NPOS/128), 128>>>(
            w, wt + QO + (size_t)d*110592, qkv_b + d * 3 * C, qkv, 3 * C, C);
        attn2_kernel<<<dim3(B * NW, HEADS), 256, ATTN_SMEM>>>(bias + (size_t)d * 98304, sh);
        gemm_mma<0,0,0><<<dim3(3, NPOS/128), 128>>>(
            o, wt + PO + (size_t)d*36864, proj_b + d * C, w, C, C);
        lnfuse_kernel<<<NPOS / 8, 256>>>(e, w, qkv, ln2_g + d * C, ln2_b + d * C, sh);
        gemm_mma<1,0,1><<<dim3(12, NPOS/128), 128>>>(
            qkv, wt + F1O + (size_t)d*147456, fc1_b + d * 4 * C, h, 4 * C, C);
        gemm_mma<0,1,0><<<dim3(3, NPOS/128), 128>>>(
            h, wt + F2O + (size_t)d*147456, fc2_b + d * C, e, C, 4 * C);
    }

    // ---- reconstruction ----
    round_copy<<<(NPOS * C / 4) / 256, 256>>>(e, w, NPOS * C / 4);
    gemm_mma<0,0,0><<<dim3(2, NPOS/128), 128>>>(w, wt + RO, zeros, qkv, 128, C);
    scatter_kernel<<<(NPOS * 128) / 256, 256>>>(qkv, rec_b, out);
}

// round 12
// speedup vs baseline: 1.4346x; 1.0374x over previous
#include <cuda_runtime.h>
#include <math.h>
#include <stdint.h>

typedef unsigned long long ull;

// ---------------- problem constants ----------------
#define B 2
#define C 192
#define HEADS 6
#define ZP 32
#define NPOS (B*ZP*ZP*ZP)          // 65536
#define NW 256
#define DEPTH 4
#define TBL 675

// weight scratch offsets (floats)
#define QO 0
#define PO 442368
#define F1O 589824
#define F2O 1179648
#define RO 1769472
#define PEO 1794048
#define WT_TOTAL 1818624

// ---------------- scratch ----------------
__device__ float g_e  [(size_t)NPOS * C];
__device__ float g_w  [(size_t)NPOS * C];
__device__ float g_qkv[(size_t)NPOS * 3 * C];
__device__ float g_o  [(size_t)NPOS * C];
__device__ float g_h  [(size_t)NPOS * 4 * C];
__device__ float g_wt [WT_TOTAL];
__device__ float g_bias[DEPTH * HEADS * 128 * 128];
__device__ float g_zeros[192];

// ---------------- helpers ----------------
__device__ __forceinline__ float gelu_f(float v){
    return 0.5f * v * (1.0f + erff(v * 0.70710678118654752f));
}
__device__ __forceinline__ void mma_tf32(float* d, const uint32_t* a, const uint32_t* b){
    asm volatile(
        "mma.sync.aligned.m16n8k8.row.col.f32.tf32.tf32.f32 "
        "{%0,%1,%2,%3}, {%4,%5,%6,%7}, {%8,%9}, {%0,%1,%2,%3};"
        : "+f"(d[0]), "+f"(d[1]), "+f"(d[2]), "+f"(d[3])
        : "r"(a[0]), "r"(a[1]), "r"(a[2]), "r"(a[3]), "r"(b[0]), "r"(b[1]));
}
__device__ __forceinline__ float tf32_rna(float x){
    uint32_t r; asm("cvt.rna.tf32.f32 %0, %1;" : "=r"(r) : "f"(x));
    return __uint_as_float(r);
}
__device__ __forceinline__ uint32_t smem_u32(const void* p){
    uint32_t a;
    asm("{ .reg .u64 t; cvta.to.shared.u64 t, %1; cvt.u32.u64 %0, t; }" : "=r"(a) : "l"(p));
    return a;
}
__device__ __forceinline__ void cp16(uint32_t d, const void* s){
    asm volatile("cp.async.cg.shared.global [%0], [%1], 16;" :: "r"(d), "l"(s));
}
__device__ __forceinline__ void cp_commit(){
    asm volatile("cp.async.commit_group;");
}
template<int Npend>
__device__ __forceinline__ void cp_wait(){
    asm volatile("cp.async.wait_group %0;" :: "n"(Npend) : "memory");
}

// ================= fused setup: weight transposes + rounding + bias table =================
__global__ void setup_kernel(const float* __restrict__ qkv_w, const float* __restrict__ proj_w,
                             const float* __restrict__ fc1_w, const float* __restrict__ fc2_w,
                             const float* __restrict__ rec_w, const float* __restrict__ pe_w,
                             const float* __restrict__ rpb)
{
    int idx = blockIdx.x * 256 + threadIdx.x;
    if (idx < 442368) {
        int d = idx / 110592, r = idx % 110592;
        int k = r / 576, n = r % 576;
        g_wt[QO + d * 110592 + n * 192 + k] = tf32_rna(qkv_w[idx]);
        return;
    }
    idx -= 442368;
    if (idx < 147456) {
        int d = idx / 36864, r = idx % 36864;
        int k = r / 192, n = r % 192;
        g_wt[PO + d * 36864 + n * 192 + k] = tf32_rna(proj_w[idx]);
        return;
    }
    idx -= 147456;
    if (idx < 589824) {
        int d = idx / 147456, r = idx % 147456;
        int k = r / 768, n = r % 768;
        g_wt[F1O + d * 147456 + n * 192 + k] = tf32_rna(fc1_w[idx]);
        return;
    }
    idx -= 589824;
    if (idx < 589824) {
        int d = idx / 147456, r = idx % 147456;
        int k = r / 192, n = r % 192;
        g_wt[F2O + d * 147456 + n * 768 + k] = tf32_rna(fc2_w[idx]);
        return;
    }
    idx -= 589824;
    if (idx < 24576) {
        int k = idx / 128, n = idx % 128;
        g_wt[RO + n * 192 + k] = tf32_rna(rec_w[idx]);
        return;
    }
    idx -= 24576;
    if (idx < 24576) {
        g_wt[PEO + idx] = tf32_rna(pe_w[idx]);
        return;
    }
    idx -= 24576;
    if (idx < DEPTH * HEADS * 16384) {
        int d = idx / 98304, r = idx % 98304;
        int h = r >> 14, n = (r >> 7) & 127, m = r & 127;
        int zn = n >> 6, hn = (n >> 3) & 7, wn = n & 7;
        int zm = m >> 6, hm = (m >> 3) & 7, wm = m & 7;
        int bi = (zn - zm + 1) * 225 + (hn - hm + 7) * 15 + (wn - wm + 7);
        g_bias[idx] = rpb[((size_t)d * TBL + bi) * HEADS + h];
    }
}
#define SETUP_TOTAL (442368 + 147456 + 589824 + 589824 + 24576 + 24576 + DEPTH*HEADS*16384)

// ================= tf32 mma.sync GEMM (pre-rounded, cp.async, single sync) =================
#define ASZB (128 * 36 * 4)
#define BSZB (64 * 36 * 4)
template<int ACT, int BETA, int ROUT, int DUAL>
__global__ __launch_bounds__(128)
void gemm_mma(const float* __restrict__ A, const float* __restrict__ Bw,
              const float* __restrict__ bias, float* __restrict__ Cm,
              float* __restrict__ Cm2, int N, int K)
{
    __shared__ float As[2][128 * 36];
    __shared__ float Bs[2][64 * 36];
    const int t = threadIdx.x;
    const int lane = t & 31, wid = t >> 5;
    const int warpM = wid * 32;
    const int g = lane >> 2, tg = lane & 3;
    const int bm = blockIdx.y << 7;
    const int bn = blockIdx.x << 6;
    const int K4 = K >> 2;
    const int nk = K >> 5;

    const float4* A4 = (const float4*)A;
    const float4* B4 = (const float4*)Bw;
    const int lrow = t >> 3;
    const int lk4  = t & 7;
    int aBase[8], aOff[8];
#pragma unroll
    for (int i = 0; i < 8; i++) {
        int row = lrow + i * 16;
        aBase[i] = (bm + row) * K4 + lk4;
        aOff[i] = (row * 36 + lk4 * 4) * 4;
    }
    int bBase[4], bOff[4];
#pragma unroll
    for (int i = 0; i < 4; i++) {
        int row = lrow + i * 16;
        bBase[i] = (bn + row) * K4 + lk4;
        bOff[i] = (row * 36 + lk4 * 4) * 4;
    }
    const uint32_t uA = smem_u32(&As[0][0]);
    const uint32_t uB = smem_u32(&Bs[0][0]);

#pragma unroll
    for (int i = 0; i < 8; i++) cp16(uA + aOff[i], &A4[aBase[i]]);
#pragma unroll
    for (int i = 0; i < 4; i++) cp16(uB + bOff[i], &B4[bBase[i]]);
    cp_commit();

    float acc[2][8][4];
#pragma unroll
    for (int mi = 0; mi < 2; mi++)
#pragma unroll
        for (int ni = 0; ni < 8; ni++)
#pragma unroll
            for (int j = 0; j < 4; j++) acc[mi][ni][j] = 0.f;

    for (int kt = 0; kt < nk; kt++) {
        cp_wait<0>();
        __syncthreads();
        const int buf = kt & 1;
        if (kt + 1 < nk) {
            const int nb = buf ^ 1;
            const int ko = (kt + 1) * 8;
#pragma unroll
            for (int i = 0; i < 8; i++) cp16(uA + nb * ASZB + aOff[i], &A4[aBase[i] + ko]);
#pragma unroll
            for (int i = 0; i < 4; i++) cp16(uB + nb * BSZB + bOff[i], &B4[bBase[i] + ko]);
            cp_commit();
        }
        const uint32_t* Asu = (const uint32_t*)As[buf];
        const uint32_t* Bsu = (const uint32_t*)Bs[buf];
#pragma unroll
        for (int ks = 0; ks < 4; ks++) {
            const int k0 = ks * 8;
            uint32_t af[2][4];
#pragma unroll
            for (int mi = 0; mi < 2; mi++) {
                int r = (warpM + mi * 16 + g) * 36 + k0 + tg;
                af[mi][0] = Asu[r];
                af[mi][1] = Asu[r + 8 * 36];
                af[mi][2] = Asu[r + 4];
                af[mi][3] = Asu[r + 8 * 36 + 4];
            }
#pragma unroll
            for (int ni = 0; ni < 8; ni++) {
                uint32_t bf[2];
                int r = (ni * 8 + g) * 36 + k0 + tg;
                bf[0] = Bsu[r];
                bf[1] = Bsu[r + 4];
                mma_tf32(acc[0][ni], af[0], bf);
                mma_tf32(acc[1][ni], af[1], bf);
            }
        }
        __syncthreads();
    }

#pragma unroll
    for (int mi = 0; mi < 2; mi++) {
        int r0 = bm + warpM + mi * 16 + g;
#pragma unroll
        for (int ni = 0; ni < 8; ni++) {
            int cb = bn + ni * 8 + 2 * tg;
            float b0 = bias[cb], b1 = bias[cb + 1];
            float v0 = acc[mi][ni][0] + b0, v1 = acc[mi][ni][1] + b1;
            float v2 = acc[mi][ni][2] + b0, v3 = acc[mi][ni][3] + b1;
            if (ACT) { v0 = gelu_f(v0); v1 = gelu_f(v1); v2 = gelu_f(v2); v3 = gelu_f(v3); }
            if (ROUT) { v0 = tf32_rna(v0); v1 = tf32_rna(v1); v2 = tf32_rna(v2); v3 = tf32_rna(v3); }
            size_t o0 = (size_t)r0 * N + cb;
            size_t o1 = (size_t)(r0 + 8) * N + cb;
            if (BETA) {
                float2 x0 = *(const float2*)&Cm[o0];
                float2 x1 = *(const float2*)&Cm[o1];
                v0 += x0.x; v1 += x0.y; v2 += x1.x; v3 += x1.y;
            }
            *(float2*)&Cm[o0] = make_float2(v0, v1);
            *(float2*)&Cm[o1] = make_float2(v2, v3);
            if (DUAL) {
                *(float2*)&Cm2[o0] = make_float2(tf32_rna(v0), tf32_rna(v1));
                *(float2*)&Cm2[o1] = make_float2(tf32_rna(v2), tf32_rna(v3));
            }
        }
    }
}

// ---------------- warp-per-token LayerNorm ----------------
__global__ __launch_bounds__(256)
void ln2_kernel(const float* __restrict__ src, float* __restrict__ dst,
                const float* __restrict__ g, const float* __restrict__ b, int mode, int rnd)
{
    const int lane = threadIdx.x & 31;
    const int tok = blockIdx.x * 8 + (threadIdx.x >> 5);
    int spos;
    if (mode == 0) {
        spos = tok;
    } else {
        int n = tok & 127, wi = (tok >> 7) & 255, bb = tok >> 15;
        int zw = wi >> 4, hw = (wi >> 2) & 3, ww = wi & 3;
        int z = zw * 2 + (n >> 6), h = hw * 8 + ((n >> 3) & 7), w = ww * 8 + (n & 7);
        if (mode == 2) { z = (z + 1) & 31; h = (h + 4) & 31; w = (w + 4) & 31; }
        spos = ((bb * 32 + z) * 32 + h) * 32 + w;
    }
    const float* sp = src + (size_t)spos * C;
    float v[6]; float s = 0.f, s2 = 0.f;
#pragma unroll
    for (int j = 0; j < 6; j++) { v[j] = sp[lane + 32*j]; s += v[j]; s2 += v[j]*v[j]; }
#pragma unroll
    for (int o = 16; o > 0; o >>= 1) {
        s  += __shfl_xor_sync(0xffffffffu, s,  o);
        s2 += __shfl_xor_sync(0xffffffffu, s2, o);
    }
    float m = s * (1.0f/192.0f);
    float rstd = rsqrtf(s2 * (1.0f/192.0f) - m*m + 1e-5f);
    float* dp = dst + (size_t)tok * C;
#pragma unroll
    for (int j = 0; j < 6; j++) {
        int c = lane + 32*j;
        float o2 = (v[j] - m) * rstd * g[c] + b[c];
        dp[c] = rnd ? tf32_rna(o2) : o2;
    }
}

// ---------------- fused window-merge + residual add + LayerNorm (dst rounded) ----------------
__global__ __launch_bounds__(256)
void lnfuse_kernel(float* __restrict__ e, const float* __restrict__ wwin,
                   float* __restrict__ dst,
                   const float* __restrict__ g, const float* __restrict__ b, int shifted)
{
    const int lane = threadIdx.x & 31;
    const int pos = blockIdx.x * 8 + (threadIdx.x >> 5);
    int ww2 = pos & 31, hh = (pos >> 5) & 31, z = (pos >> 10) & 31, bb = pos >> 15;
    int sz = shifted ? 1 : 0, s4 = shifted ? 4 : 0;
    int z2 = (z - sz) & 31, h2 = (hh - s4) & 31, w2 = (ww2 - s4) & 31;
    int wi = ((z2 >> 1) << 4) | ((h2 >> 3) << 2) | (w2 >> 3);
    int n  = ((z2 & 1) << 6) | ((h2 & 7) << 3) | (w2 & 7);
    int tok = (bb * 256 + wi) * 128 + n;

    float* ep = e + (size_t)pos * C;
    const float* wp = wwin + (size_t)tok * C;
    float v[6]; float s = 0.f, s2 = 0.f;
#pragma unroll
    for (int j = 0; j < 6; j++) {
        int c = lane + 32*j;
        float a = ep[c] + wp[c];
        ep[c] = a;
        v[j] = a; s += a; s2 += a*a;
    }
#pragma unroll
    for (int o = 16; o > 0; o >>= 1) {
        s  += __shfl_xor_sync(0xffffffffu, s,  o);
        s2 += __shfl_xor_sync(0xffffffffu, s2, o);
    }
    float m = s * (1.0f/192.0f);
    float rstd = rsqrtf(s2 * (1.0f/192.0f) - m*m + 1e-5f);
    float* dp = dst + (size_t)pos * C;
#pragma unroll
    for (int j = 0; j < 6; j++) {
        int c = lane + 32*j;
        dp[c] = tf32_rna((v[j] - m) * rstd * g[c] + b[c]);
    }
}

// ---------------- window attention: full tf32 MMA (QK^T and AV) ----------------
// smem floats: Qn[128][36], Kn[128][36], Vt[32][132], Ss[128][132], rid[128]
#define OQ 0
#define OK_ 4608
#define OV 9216
#define OS 13440
#define ORID 30336
#define ATTN_SMEM_F 30472

__global__ __launch_bounds__(256)
void attn2_kernel(const float* __restrict__ biasT, int shifted)
{
    extern __shared__ float sm[];
    float* Qn = sm + OQ;          // [n][36] token-major (rounded, scaled)
    float* Kn = sm + OK_;         // [m][36] token-major (rounded)
    float* Vt = sm + OV;          // [d][132] d-major (rounded)
    float* Ss = sm + OS;          // [n][132]
    int* rid_s = (int*)(sm + ORID);

    const int win = blockIdx.x;
    const int hh  = blockIdx.y;
    const int t = threadIdx.x;
    const int lane = t & 31, wid = t >> 5;
    const int g = lane >> 2, tg = lane & 3;
    const float scale = 0.1767766952966369f;
    const float* bl = biasT + (size_t)hh * 16384;

    for (int e = t; e < 4096; e += 256) {
        int n = e >> 5, d = e & 31;
        size_t base = ((size_t)(win * 128 + n)) * (3 * C) + hh * 32 + d;
        Qn[n * 36 + d] = tf32_rna(g_qkv[base] * scale);
        Kn[n * 36 + d] = tf32_rna(g_qkv[base + C]);
        Vt[d * 132 + n] = tf32_rna(g_qkv[base + 2 * C]);
    }
    int wloc = win & 255;
    int zw = wloc >> 4, hw = (wloc >> 2) & 3, ww = wloc & 3;
    if (shifted && t < 128) {
        int z = zw * 2 + (t >> 6), h = hw * 8 + ((t >> 3) & 7), w = ww * 8 + (t & 7);
        rid_s[t] = (z < 30 ? 0 : (z < 31 ? 1 : 2)) * 9
                 + (h < 24 ? 0 : (h < 28 ? 1 : 2)) * 3
                 + (w < 24 ? 0 : (w < 28 ? 1 : 2));
    }
    __syncthreads();

    // ---- S = QK^T via tf32 mma: warp w -> rows [16w, 16w+16), all 128 cols ----
    {
        float sacc[16][4];
#pragma unroll
        for (int mi = 0; mi < 16; mi++)
#pragma unroll
            for (int j = 0; j < 4; j++) sacc[mi][j] = 0.f;
        const uint32_t* Qu = (const uint32_t*)Qn;
        const uint32_t* Ku = (const uint32_t*)Kn;
#pragma unroll
        for (int ks = 0; ks < 4; ks++) {
            const int k0 = ks * 8;
            uint32_t af[4];
            int ra = (wid * 16 + g) * 36 + k0 + tg;
            af[0] = Qu[ra];
            af[1] = Qu[ra + 8 * 36];
            af[2] = Qu[ra + 4];
            af[3] = Qu[ra + 8 * 36 + 4];
#pragma unroll
            for (int mi = 0; mi < 16; mi++) {
                uint32_t bf[2];
                int rb = (mi * 8 + g) * 36 + k0 + tg;
                bf[0] = Ku[rb];
                bf[1] = Ku[rb + 4];
                mma_tf32(sacc[mi], af, bf);
            }
        }
        // bias + mask + store
        int n0 = wid * 16 + g;
        int ridn0 = shifted ? rid_s[n0] : 0;
        int ridn1 = shifted ? rid_s[n0 + 8] : 0;
#pragma unroll
        for (int mi = 0; mi < 16; mi++) {
            int mb = mi * 8 + 2 * tg;
            float2 b0 = *(const float2*)&bl[n0 * 128 + mb];
            float2 b1 = *(const float2*)&bl[(n0 + 8) * 128 + mb];
            float v0 = sacc[mi][0] + b0.x, v1 = sacc[mi][1] + b0.y;
            float v2 = sacc[mi][2] + b1.x, v3 = sacc[mi][3] + b1.y;
            if (shifted) {
                int rm0 = rid_s[mb], rm1 = rid_s[mb + 1];
                if (rm0 != ridn0) v0 -= 100.0f;
                if (rm1 != ridn0) v1 -= 100.0f;
                if (rm0 != ridn1) v2 -= 100.0f;
                if (rm1 != ridn1) v3 -= 100.0f;
            }
            *(float2*)&Ss[n0 * 132 + mb] = make_float2(v0, v1);
            *(float2*)&Ss[(n0 + 8) * 132 + mb] = make_float2(v2, v3);
        }
    }
    __syncthreads();

    // ---- softmax (rounds P to tf32) ----
    {
        int n = t >> 1, half = t & 1;
        float* row = &Ss[n * 132 + half * 64];
        float mx = -1e30f;
#pragma unroll
        for (int j = 0; j < 16; j++) {
            float4 v = *(const float4*)&row[j * 4];
            mx = fmaxf(mx, fmaxf(fmaxf(v.x, v.y), fmaxf(v.z, v.w)));
        }
        mx = fmaxf(mx, __shfl_xor_sync(0xffffffffu, mx, 1));
        float sum = 0.f;
#pragma unroll
        for (int j = 0; j < 16; j++) {
            float4 v = *(float4*)&row[j * 4];
            v.x = __expf(v.x - mx); v.y = __expf(v.y - mx);
            v.z = __expf(v.z - mx); v.w = __expf(v.w - mx);
            sum += v.x + v.y + v.z + v.w;
            *(float4*)&row[j * 4] = v;
        }
        sum += __shfl_xor_sync(0xffffffffu, sum, 1);
        float inv = 1.0f / sum;
#pragma unroll
        for (int j = 0; j < 16; j++) {
            float4 v = *(float4*)&row[j * 4];
            v.x = tf32_rna(v.x * inv); v.y = tf32_rna(v.y * inv);
            v.z = tf32_rna(v.z * inv); v.w = tf32_rna(v.w * inv);
            *(float4*)&row[j * 4] = v;
        }
    }
    __syncthreads();

    // ---- O = P @ V via tf32 mma ----
    {
        float av[4][4];
#pragma unroll
        for (int ni = 0; ni < 4; ni++)
#pragma unroll
            for (int j = 0; j < 4; j++) av[ni][j] = 0.f;
        const uint32_t* Ps = (const uint32_t*)Ss;
        const uint32_t* Vu = (const uint32_t*)Vt;
#pragma unroll
        for (int ks = 0; ks < 16; ks++) {
            const int k0 = ks * 8;
            uint32_t af[4];
            int ra = (wid * 16 + g) * 132 + k0 + tg;
            af[0] = Ps[ra];
            af[1] = Ps[ra + 8 * 132];
            af[2] = Ps[ra + 4];
            af[3] = Ps[ra + 8 * 132 + 4];
#pragma unroll
            for (int ni = 0; ni < 4; ni++) {
                uint32_t bf[2];
                int rb = (ni * 8 + g) * 132 + k0 + tg;
                bf[0] = Vu[rb];
                bf[1] = Vu[rb + 4];
                mma_tf32(av[ni], af, bf);
            }
        }
#pragma unroll
        for (int ni = 0; ni < 4; ni++) {
            int n0 = wid * 16 + g;
            int d = ni * 8 + 2 * tg;
            size_t o0 = ((size_t)(win * 128 + n0)) * C + hh * 32 + d;
            size_t o1 = ((size_t)(win * 128 + n0 + 8)) * C + hh * 32 + d;
            *(float2*)&g_o[o0] = make_float2(tf32_rna(av[ni][0]), tf32_rna(av[ni][1]));
            *(float2*)&g_o[o1] = make_float2(tf32_rna(av[ni][2]), tf32_rna(av[ni][3]));
        }
    }
}

// ---------------- patch-embed gather (rounded) / recon scatter ----------------
__global__ void gather_kernel(const float* __restrict__ x, float* __restrict__ xg)
{
    int idx = blockIdx.x * blockDim.x + threadIdx.x;
    if (idx >= NPOS * 128) return;
    int t = idx & 127, pos = idx >> 7;
    int w = pos & 31, h = (pos >> 5) & 31, z = (pos >> 10) & 31, b = pos >> 15;
    int c4 = t >> 5, i = (t >> 4) & 1, j = (t >> 2) & 3, k = t & 3;
    xg[idx] = tf32_rna(x[((((size_t)b * 4 + c4) * 64 + 2 * z + i) * 128 + 4 * h + j) * 128 + 4 * w + k]);
}

__global__ void scatter_kernel(const float* __restrict__ rec, const float* __restrict__ rec_b,
                               float* __restrict__ out)
{
    int idx = blockIdx.x * blockDim.x + threadIdx.x;
    if (idx >= NPOS * 128) return;
    int t = idx & 127, pos = idx >> 7;
    int w = pos & 31, h = (pos >> 5) & 31, z = (pos >> 10) & 31, b = pos >> 15;
    int o = t >> 5, i = (t >> 4) & 1, j = (t >> 2) & 3, k = t & 3;
    out[((((size_t)b * 4 + o) * 64 + 2 * z + i) * 128 + 4 * h + j) * 128 + 4 * w + k]
        = rec[idx] + rec_b[o];
}

// ---------------- host launcher ----------------
extern "C" void kernel_launch(void* const* d_in, const int* in_sizes, int n_in,
                              void* d_out, int out_size)
{
    const float* x       = (const float*)d_in[0];
    const float* pe_w    = (const float*)d_in[1];
    const float* pe_b    = (const float*)d_in[2];
    const float* pe_ln_g = (const float*)d_in[3];
    const float* pe_ln_b = (const float*)d_in[4];
    const float* ln1_g   = (const float*)d_in[5];
    const float* ln1_b   = (const float*)d_in[6];
    const float* qkv_w   = (const float*)d_in[7];
    const float* qkv_b   = (const float*)d_in[8];
    const float* proj_w  = (const float*)d_in[9];
    const float* proj_b  = (const float*)d_in[10];
    const float* rpb     = (const float*)d_in[11];
    const float* ln2_g   = (const float*)d_in[12];
    const float* ln2_b   = (const float*)d_in[13];
    const float* fc1_w   = (const float*)d_in[14];
    const float* fc1_b   = (const float*)d_in[15];
    const float* fc2_w   = (const float*)d_in[16];
    const float* fc2_b   = (const float*)d_in[17];
    const float* rec_w   = (const float*)d_in[18];
    const float* rec_b   = (const float*)d_in[19];
    float* out = (float*)d_out;

    float *e, *w, *qkv, *h, *o, *wt, *bias, *zeros;
    cudaGetSymbolAddress((void**)&e,     g_e);
    cudaGetSymbolAddress((void**)&w,     g_w);
    cudaGetSymbolAddress((void**)&qkv,   g_qkv);
    cudaGetSymbolAddress((void**)&h,     g_h);
    cudaGetSymbolAddress((void**)&o,     g_o);
    cudaGetSymbolAddress((void**)&wt,    g_wt);
    cudaGetSymbolAddress((void**)&bias,  g_bias);
    cudaGetSymbolAddress((void**)&zeros, g_zeros);

    const int ATTN_SMEM = ATTN_SMEM_F * (int)sizeof(float);
    cudaFuncSetAttribute(attn2_kernel, cudaFuncAttributeMaxDynamicSharedMemorySize, ATTN_SMEM);

    setup_kernel<<<(SETUP_TOTAL + 255) / 256, 256>>>(qkv_w, proj_w, fc1_w, fc2_w, rec_w, pe_w, rpb);

    gather_kernel<<<(NPOS * 128) / 256, 256>>>(x, h);
    gemm_mma<0,0,0,0><<<dim3(3, NPOS/128), 128>>>(h, wt + PEO, pe_b, w, e, 192, 128);
    ln2_kernel<<<NPOS / 8, 256>>>(w, e, pe_ln_g, pe_ln_b, 0, 0);

    for (int d = 0; d < DEPTH; d++) {
        int sh = d & 1;
        ln2_kernel<<<NPOS / 8, 256>>>(e, w, ln1_g + d * C, ln1_b + d * C, sh ? 2 : 1, 1);
        gemm_mma<0,0,0,0><<<dim3(9, NPOS/128), 128>>>(
            w, wt + QO + (size_t)d*110592, qkv_b + d * 3 * C, qkv, e, 3 * C, C);
        attn2_kernel<<<dim3(B * NW, HEADS), 256, ATTN_SMEM>>>(bias + (size_t)d * 98304, sh);
        gemm_mma<0,0,0,0><<<dim3(3, NPOS/128), 128>>>(
            o, wt + PO + (size_t)d*36864, proj_b + d * C, w, e, C, C);
        lnfuse_kernel<<<NPOS / 8, 256>>>(e, w, qkv, ln2_g + d * C, ln2_b + d * C, sh);
        gemm_mma<1,0,1,0><<<dim3(12, NPOS/128), 128>>>(
            qkv, wt + F1O + (size_t)d*147456, fc1_b + d * 4 * C, h, e, 4 * C, C);
        if (d < DEPTH - 1) {
            gemm_mma<0,1,0,0><<<dim3(3, NPOS/128), 128>>>(
                h, wt + F2O + (size_t)d*147456, fc2_b + d * C, e, w, C, 4 * C);
        } else {
            // last layer: also emit rounded copy of e into w for the recon GEMM
            gemm_mma<0,1,0,1><<<dim3(3, NPOS/128), 128>>>(
                h, wt + F2O + (size_t)d*147456, fc2_b + d * C, e, w, C, 4 * C);
        }
    }

    gemm_mma<0,0,0,0><<<dim3(2, NPOS/128), 128>>>(w, wt + RO, zeros, qkv, e, 128, C);
    scatter_kernel<<<(NPOS * 128) / 256, 256>>>(qkv, rec_b, out);
}